// round 10
// baseline (speedup 1.0000x reference)
#include <cuda_runtime.h>
#include <math.h>

#define NB 2
#define NT 2048
#define NC 768
#define NH 12
#define ND 64
#define QKVW 2304
#define NCHUNK 16
#define CHROWS 128

// ---------------- scratch (device globals; no allocation allowed) ----------
__device__ float g_qkv[(size_t)NB * NT * QKVW];       // [B*T, 2304]
__device__ float g_S[(size_t)NB * NT * NT];           // head-0 masked relu scores
__device__ float g_F[(size_t)NB * NT * NT];           // exclusive column cumsum
__device__ float g_csum[NB * NCHUNK * NT];            // chunk column sums
__device__ float g_y[(size_t)NB * NT * (NH * ND)];    // attention output [B*T, 768]

// ---------------------------------------------------------------------------
// SGEMM-NT + bias:  C[m,n] = sum_k A[m,k] * Bw[n,k] + bias[n]
// BM=BN=128, BK=16, 256 threads, 8x8 per thread.
// Requires M%128==0, N%128==0, K%16==0 (true for all uses here).
// ---------------------------------------------------------------------------
__global__ __launch_bounds__(256) void sgemm_nt_bias(
    const float* __restrict__ A, const float* __restrict__ Bw,
    const float* __restrict__ bias, float* __restrict__ Co,
    int M, int N, int K)
{
    __shared__ float As[16][128];
    __shared__ float Bs[16][128];
    const int bm = blockIdx.y * 128;
    const int bn = blockIdx.x * 128;
    const int tid = threadIdx.x;
    const int ty = tid >> 4, tx = tid & 15;
    const int lr = tid >> 1;            // 0..127
    const int lc = (tid & 1) << 3;      // 0 or 8

    float acc[8][8];
#pragma unroll
    for (int r = 0; r < 8; r++)
#pragma unroll
        for (int c = 0; c < 8; c++) acc[r][c] = 0.f;

    const float* Ap = A + (size_t)(bm + lr) * K + lc;
    const float* Bp = Bw + (size_t)(bn + lr) * K + lc;

    for (int k0 = 0; k0 < K; k0 += 16) {
        float4 a0 = *(const float4*)(Ap + k0);
        float4 a1 = *(const float4*)(Ap + k0 + 4);
        float4 b0 = *(const float4*)(Bp + k0);
        float4 b1 = *(const float4*)(Bp + k0 + 4);
        __syncthreads();
        As[lc + 0][lr] = a0.x; As[lc + 1][lr] = a0.y; As[lc + 2][lr] = a0.z; As[lc + 3][lr] = a0.w;
        As[lc + 4][lr] = a1.x; As[lc + 5][lr] = a1.y; As[lc + 6][lr] = a1.z; As[lc + 7][lr] = a1.w;
        Bs[lc + 0][lr] = b0.x; Bs[lc + 1][lr] = b0.y; Bs[lc + 2][lr] = b0.z; Bs[lc + 3][lr] = b0.w;
        Bs[lc + 4][lr] = b1.x; Bs[lc + 5][lr] = b1.y; Bs[lc + 6][lr] = b1.z; Bs[lc + 7][lr] = b1.w;
        __syncthreads();
#pragma unroll
        for (int kk = 0; kk < 16; kk++) {
            float af[8], bf[8];
            *(float4*)&af[0] = *(const float4*)&As[kk][ty * 8];
            *(float4*)&af[4] = *(const float4*)&As[kk][ty * 8 + 4];
            *(float4*)&bf[0] = *(const float4*)&Bs[kk][tx * 8];
            *(float4*)&bf[4] = *(const float4*)&Bs[kk][tx * 8 + 4];
#pragma unroll
            for (int r = 0; r < 8; r++)
#pragma unroll
                for (int c = 0; c < 8; c++) acc[r][c] += af[r] * bf[c];
        }
    }

    float bv[8];
#pragma unroll
    for (int c = 0; c < 8; c++) bv[c] = bias[bn + tx * 8 + c];
#pragma unroll
    for (int r = 0; r < 8; r++) {
        int row = bm + ty * 8 + r;
        float4 o0, o1;
        o0.x = acc[r][0] + bv[0]; o0.y = acc[r][1] + bv[1];
        o0.z = acc[r][2] + bv[2]; o0.w = acc[r][3] + bv[3];
        o1.x = acc[r][4] + bv[4]; o1.y = acc[r][5] + bv[5];
        o1.z = acc[r][6] + bv[6]; o1.w = acc[r][7] + bv[7];
        *(float4*)&Co[(size_t)row * N + bn + tx * 8] = o0;
        *(float4*)&Co[(size_t)row * N + bn + tx * 8 + 4] = o1;
    }
}

// ---------------------------------------------------------------------------
// Head-0 selection scores: S[b,i,j] = (1<=j<i) ? max(0, 0.125*q0[i].k0[j]) : 0
// 64x64 tile per block; blocks with jt>it just write zeros.
// ---------------------------------------------------------------------------
__global__ __launch_bounds__(256) void score0_kernel()
{
    const int jt = blockIdx.x, it = blockIdx.y, b = blockIdx.z;
    const int tid = threadIdx.x;
    const int ty = tid >> 4, tx = tid & 15;

    if (jt > it) {
        float4 z = make_float4(0.f, 0.f, 0.f, 0.f);
#pragma unroll
        for (int l = 0; l < 4; l++) {
            int lin = tid + l * 256;
            int r = lin >> 4, cg = (lin & 15) << 2;
            *(float4*)&g_S[((size_t)(b * NT) + it * 64 + r) * NT + jt * 64 + cg] = z;
        }
        return;
    }

    __shared__ float qts[64 * 68];
    __shared__ float kts[64 * 68];
    const float* qb = g_qkv + ((size_t)(b * NT) + it * 64) * QKVW;        // q head 0
    const float* kb = g_qkv + ((size_t)(b * NT) + jt * 64) * QKVW + 768;  // k head 0
#pragma unroll
    for (int l = 0; l < 4; l++) {
        int lin = tid + l * 256;
        int r = lin >> 4, dg = (lin & 15) << 2;
        float4 qv = *(const float4*)&qb[(size_t)r * QKVW + dg];
        qts[(dg + 0) * 68 + r] = qv.x; qts[(dg + 1) * 68 + r] = qv.y;
        qts[(dg + 2) * 68 + r] = qv.z; qts[(dg + 3) * 68 + r] = qv.w;
        float4 kv = *(const float4*)&kb[(size_t)r * QKVW + dg];
        kts[(dg + 0) * 68 + r] = kv.x; kts[(dg + 1) * 68 + r] = kv.y;
        kts[(dg + 2) * 68 + r] = kv.z; kts[(dg + 3) * 68 + r] = kv.w;
    }
    __syncthreads();

    float s[4][4];
#pragma unroll
    for (int r = 0; r < 4; r++)
#pragma unroll
        for (int c = 0; c < 4; c++) s[r][c] = 0.f;

#pragma unroll 16
    for (int d = 0; d < 64; d++) {
        float4 qa = *(const float4*)&qts[d * 68 + ty * 4];
        float4 ka = *(const float4*)&kts[d * 68 + tx * 4];
        float qr[4] = {qa.x, qa.y, qa.z, qa.w};
        float kr[4] = {ka.x, ka.y, ka.z, ka.w};
#pragma unroll
        for (int r = 0; r < 4; r++)
#pragma unroll
            for (int c = 0; c < 4; c++) s[r][c] += qr[r] * kr[c];
    }

#pragma unroll
    for (int r = 0; r < 4; r++) {
        int i = it * 64 + ty * 4 + r;
        float o[4];
#pragma unroll
        for (int c = 0; c < 4; c++) {
            int j = jt * 64 + tx * 4 + c;
            float v = s[r][c] * 0.125f;
            o[c] = (j >= 1 && j < i) ? fmaxf(v, 0.f) : 0.f;
        }
        *(float4*)&g_S[((size_t)(b * NT) + i) * NT + jt * 64 + tx * 4] =
            make_float4(o[0], o[1], o[2], o[3]);
    }
}

// ---------------------------------------------------------------------------
// Column scan:  F[b,i,j] = sum_{i'<i} S[b,i',j]
// Two-pass: chunk column sums (128-row chunks), then sequential scan per chunk.
// ---------------------------------------------------------------------------
__global__ __launch_bounds__(256) void colsum_kernel()
{
    int j = blockIdx.x * 256 + threadIdx.x;
    int b = blockIdx.y >> 4, ch = blockIdx.y & 15;
    const float* p = g_S + ((size_t)(b * NT) + ch * CHROWS) * NT + j;
    float s = 0.f;
    for (int r = 0; r < CHROWS; r++) s += p[(size_t)r * NT];
    g_csum[(b * NCHUNK + ch) * NT + j] = s;
}

__global__ __launch_bounds__(256) void scan_kernel()
{
    int j = blockIdx.x * 256 + threadIdx.x;
    int b = blockIdx.y >> 4, ch = blockIdx.y & 15;
    float run = 0.f;
    for (int c = 0; c < ch; c++) run += g_csum[(b * NCHUNK + c) * NT + j];
    size_t base = ((size_t)(b * NT) + ch * CHROWS) * NT + j;
    for (int r = 0; r < CHROWS; r++) {
        size_t idx = base + (size_t)r * NT;
        float sv = g_S[idx];
        g_F[idx] = run;
        run += sv;
    }
}

// ---------------------------------------------------------------------------
// Fused attention (per batch, head, 64-query tile), flash-style online
// softmax, logits = 0.125*qk - F, causal mask. Output -> g_y [B*T, 768].
// Dynamic smem: qts[64][68] (d-major), kts[64][68] (d-major; reused as p
// transposed [col][row]), vs[64][68] (kk-major).
// ---------------------------------------------------------------------------
__global__ __launch_bounds__(256) void attn_kernel()
{
    extern __shared__ float sm[];
    float* qts = sm;
    float* kts = sm + 64 * 68;
    float* vs  = sm + 2 * 64 * 68;

    const int qt = gridDim.x - 1 - blockIdx.x;   // long blocks first
    const int h = blockIdx.y, b = blockIdx.z;
    const int tid = threadIdx.x;
    const int ty = tid >> 4, tx = tid & 15;
    const int i0 = qt * 64;

    const float* qb = g_qkv + ((size_t)(b * NT) + i0) * QKVW + h * ND;
#pragma unroll
    for (int l = 0; l < 4; l++) {
        int lin = tid + l * 256;
        int r = lin >> 4, dg = (lin & 15) << 2;
        float4 qv = *(const float4*)&qb[(size_t)r * QKVW + dg];
        qts[(dg + 0) * 68 + r] = qv.x; qts[(dg + 1) * 68 + r] = qv.y;
        qts[(dg + 2) * 68 + r] = qv.z; qts[(dg + 3) * 68 + r] = qv.w;
    }

    float m[4], lsum[4], acc[4][4];
#pragma unroll
    for (int r = 0; r < 4; r++) {
        m[r] = -INFINITY; lsum[r] = 0.f;
#pragma unroll
        for (int c = 0; c < 4; c++) acc[r][c] = 0.f;
    }

    for (int kt = 0; kt <= qt; kt++) {
        __syncthreads();  // prior-iter pts/vs reads done; qts writes visible
        const float* kb = g_qkv + ((size_t)(b * NT) + kt * 64) * QKVW + 768 + h * ND;
        const float* vb = kb + 768;
#pragma unroll
        for (int l = 0; l < 4; l++) {
            int lin = tid + l * 256;
            int r = lin >> 4, dg = (lin & 15) << 2;
            float4 kv = *(const float4*)&kb[(size_t)r * QKVW + dg];
            kts[(dg + 0) * 68 + r] = kv.x; kts[(dg + 1) * 68 + r] = kv.y;
            kts[(dg + 2) * 68 + r] = kv.z; kts[(dg + 3) * 68 + r] = kv.w;
            float4 vv = *(const float4*)&vb[(size_t)r * QKVW + dg];
            *(float4*)&vs[r * 68 + dg] = vv;
        }
        __syncthreads();

        float s[4][4];
#pragma unroll
        for (int r = 0; r < 4; r++)
#pragma unroll
            for (int c = 0; c < 4; c++) s[r][c] = 0.f;

#pragma unroll 16
        for (int d = 0; d < 64; d++) {
            float4 qa = *(const float4*)&qts[d * 68 + ty * 4];
            float4 ka = *(const float4*)&kts[d * 68 + tx * 4];
            float qr[4] = {qa.x, qa.y, qa.z, qa.w};
            float kr[4] = {ka.x, ka.y, ka.z, ka.w};
#pragma unroll
            for (int r = 0; r < 4; r++)
#pragma unroll
                for (int c = 0; c < 4; c++) s[r][c] += qr[r] * kr[c];
        }

#pragma unroll
        for (int r = 0; r < 4; r++) {
            int i = i0 + ty * 4 + r;
            float4 fr = *(const float4*)&g_F[((size_t)(b * NT) + i) * NT + kt * 64 + tx * 4];
            float fv[4] = {fr.x, fr.y, fr.z, fr.w};
            float mt = -INFINITY;
#pragma unroll
            for (int c = 0; c < 4; c++) {
                int j = kt * 64 + tx * 4 + c;
                float v = s[r][c] * 0.125f - fv[c];
                if (kt == qt && j > i) v = -INFINITY;
                s[r][c] = v;
                mt = fmaxf(mt, v);
            }
#pragma unroll
            for (int off = 8; off >= 1; off >>= 1)
                mt = fmaxf(mt, __shfl_xor_sync(0xffffffffu, mt, off));
            float mn = fmaxf(m[r], mt);
            float sc = __expf(m[r] - mn);
            float rs = 0.f;
#pragma unroll
            for (int c = 0; c < 4; c++) {
                float p = __expf(s[r][c] - mn);
                s[r][c] = p;
                rs += p;
            }
#pragma unroll
            for (int off = 8; off >= 1; off >>= 1)
                rs += __shfl_xor_sync(0xffffffffu, rs, off);
            lsum[r] = lsum[r] * sc + rs;
            m[r] = mn;
#pragma unroll
            for (int c = 0; c < 4; c++) acc[r][c] *= sc;
        }

        __syncthreads();  // everyone done reading kts before overwrite with p
#pragma unroll
        for (int c = 0; c < 4; c++)
#pragma unroll
            for (int r = 0; r < 4; r++)
                kts[(tx * 4 + c) * 68 + ty * 4 + r] = s[r][c];
        __syncthreads();

#pragma unroll 16
        for (int kk = 0; kk < 64; kk++) {
            float4 pa = *(const float4*)&kts[kk * 68 + ty * 4];
            float4 va = *(const float4*)&vs[kk * 68 + tx * 4];
            float pr[4] = {pa.x, pa.y, pa.z, pa.w};
            float vr[4] = {va.x, va.y, va.z, va.w};
#pragma unroll
            for (int r = 0; r < 4; r++)
#pragma unroll
                for (int c = 0; c < 4; c++) acc[r][c] += pr[r] * vr[c];
        }
    }

#pragma unroll
    for (int r = 0; r < 4; r++) {
        int i = i0 + ty * 4 + r;
        float inv = 1.0f / lsum[r];
        float4 o = make_float4(acc[r][0] * inv, acc[r][1] * inv,
                               acc[r][2] * inv, acc[r][3] * inv);
        *(float4*)&g_y[((size_t)(b * NT) + i) * (NH * ND) + h * ND + tx * 4] = o;
    }
}

// ---------------------------------------------------------------------------
extern "C" void kernel_launch(void* const* d_in, const int* in_sizes, int n_in,
                              void* d_out, int out_size)
{
    (void)in_sizes; (void)n_in; (void)out_size;
    const float* x      = (const float*)d_in[0];
    const float* w_attn = (const float*)d_in[1];
    const float* b_attn = (const float*)d_in[2];
    const float* w_proj = (const float*)d_in[3];
    const float* b_proj = (const float*)d_in[4];
    float* out = (float*)d_out;

    float *qkv = nullptr, *y = nullptr;
    cudaGetSymbolAddress((void**)&qkv, g_qkv);
    cudaGetSymbolAddress((void**)&y, g_y);

    const int attn_smem = 3 * 64 * 68 * 4;  // 52,224 B > 48K default
    cudaFuncSetAttribute(attn_kernel,
                         cudaFuncAttributeMaxDynamicSharedMemorySize, attn_smem);

    // 1) QKV projection: [4096,768] x [2304,768]^T + b_attn -> g_qkv
    sgemm_nt_bias<<<dim3(QKVW / 128, (NB * NT) / 128), 256>>>(
        x, w_attn, b_attn, qkv, NB * NT, QKVW, NC);

    // 2) head-0 masked relu scores -> g_S
    score0_kernel<<<dim3(NT / 64, NT / 64, NB), 256>>>();

    // 3) exclusive column cumsum -> g_F
    colsum_kernel<<<dim3(NT / 256, NB * NCHUNK), 256>>>();
    scan_kernel<<<dim3(NT / 256, NB * NCHUNK), 256>>>();

    // 4) fused selective attention -> g_y
    attn_kernel<<<dim3(NT / 64, NH, NB), 256, attn_smem>>>();

    // 5) output projection: [4096,768] x [768,768]^T + b_proj -> out
    sgemm_nt_bias<<<dim3(NC / 128, (NB * NT) / 128), 256>>>(
        y, w_proj, b_proj, out, NB * NT, NC, NC);
}

// round 12
// speedup vs baseline: 1.3606x; 1.3606x over previous
#include <cuda_runtime.h>
#include <cuda_bf16.h>
#include <math.h>
#include <stdint.h>

#define NB 2
#define NT 2048
#define NC 768
#define NH 12
#define ND 64
#define QKVW 2304
#define NCHUNK 64
#define CHROWS 32

// ---------------- scratch (device globals; no allocation allowed) ----------
__device__ __align__(256) float g_qkv[(size_t)NB * NT * QKVW];
__device__ __align__(256) float g_S[(size_t)NB * NT * NT];
__device__ __align__(256) float g_F[(size_t)NB * NT * NT];
__device__ __align__(256) float g_csum[NB * NCHUNK * NT];
__device__ __align__(256) float g_y[(size_t)NB * NT * (NH * ND)];
// split-bf16 copies
__device__ __align__(256) __nv_bfloat16 g_xh[(size_t)NB * NT * NC];
__device__ __align__(256) __nv_bfloat16 g_xl[(size_t)NB * NT * NC];
__device__ __align__(256) __nv_bfloat16 g_wah[(size_t)QKVW * NC];
__device__ __align__(256) __nv_bfloat16 g_wal[(size_t)QKVW * NC];
__device__ __align__(256) __nv_bfloat16 g_wph[(size_t)NC * NC];
__device__ __align__(256) __nv_bfloat16 g_wpl[(size_t)NC * NC];
__device__ __align__(256) __nv_bfloat16 g_yh[(size_t)NB * NT * NC];
__device__ __align__(256) __nv_bfloat16 g_yl[(size_t)NB * NT * NC];

// =========================== warp-MMA helpers (sm_80+ PTX) =================
__device__ __forceinline__ uint32_t smem_u32(const void* p) {
    uint32_t a;
    asm("{ .reg .u64 t; cvta.to.shared.u64 t, %1; cvt.u32.u64 %0, t; }" : "=r"(a) : "l"(p));
    return a;
}
__device__ __forceinline__ void mma16816(float* d, const uint32_t* a, const uint32_t* b) {
    asm volatile("mma.sync.aligned.m16n8k16.row.col.f32.bf16.bf16.f32 "
        "{%0,%1,%2,%3}, {%4,%5,%6,%7}, {%8,%9}, {%0,%1,%2,%3};"
        : "+f"(d[0]), "+f"(d[1]), "+f"(d[2]), "+f"(d[3])
        : "r"(a[0]), "r"(a[1]), "r"(a[2]), "r"(a[3]), "r"(b[0]), "r"(b[1]));
}
__device__ __forceinline__ void ldsm_x4(uint32_t* r, uint32_t addr) {
    asm volatile("ldmatrix.sync.aligned.m8n8.x4.shared.b16 {%0,%1,%2,%3}, [%4];"
        : "=r"(r[0]), "=r"(r[1]), "=r"(r[2]), "=r"(r[3]) : "r"(addr));
}
__device__ __forceinline__ void ldsm_x2(uint32_t* r, uint32_t addr) {
    asm volatile("ldmatrix.sync.aligned.m8n8.x2.shared.b16 {%0,%1}, [%2];"
        : "=r"(r[0]), "=r"(r[1]) : "r"(addr));
}
__device__ __forceinline__ void cp16(uint32_t dst, const void* src) {
    asm volatile("cp.async.cg.shared.global [%0], [%1], 16;" :: "r"(dst), "l"(src));
}

// ---------------------------------------------------------------------------
// convert fp32 -> (hi bf16, lo bf16)
// ---------------------------------------------------------------------------
__global__ __launch_bounds__(256) void convert_hilo(
    const float* __restrict__ src, __nv_bfloat16* __restrict__ h,
    __nv_bfloat16* __restrict__ l, int n4)
{
    int i = blockIdx.x * 256 + threadIdx.x;
    if (i >= n4) return;
    float4 v = ((const float4*)src)[i];
    float vs[4] = {v.x, v.y, v.z, v.w};
    uint32_t hb[4], lb[4];
#pragma unroll
    for (int c = 0; c < 4; c++) {
        __nv_bfloat16 hh = __float2bfloat16(vs[c]);
        __nv_bfloat16 ll = __float2bfloat16(vs[c] - __bfloat162float(hh));
        hb[c] = __bfloat16_as_ushort(hh);
        lb[c] = __bfloat16_as_ushort(ll);
    }
    uint2 ho, lo;
    ho.x = hb[0] | (hb[1] << 16); ho.y = hb[2] | (hb[3] << 16);
    lo.x = lb[0] | (lb[1] << 16); lo.y = lb[2] | (lb[3] << 16);
    *(uint2*)(h + (size_t)i * 4) = ho;
    *(uint2*)(l + (size_t)i * 4) = lo;
}

// ---------------------------------------------------------------------------
// split-bf16 GEMM-NT + bias via mma.sync: C[m,n] = sum_k A[m,k]*B[n,k]+bias[n]
// A = Ah+Al, B = Bh+Bl; D = Ah*Bh + Ah*Bl + Al*Bh (fp32 accum).
// CTA tile 128x128, 8 warps in 2x4 (warp tile 64x32), BK=32,
// cp.async double-buffered SMEM, row pitch 80B (ldmatrix conflict-free).
// ---------------------------------------------------------------------------
#define APITCH 80
#define TILE_SB (128 * APITCH)           // 10240 B per tile
#define BUF_SB  (4 * TILE_SB)            // Ah, Al, Bh, Bl
#define GEMM_SMEM (2 * BUF_SB)           // 81920 B

__global__ __launch_bounds__(256) void gemm_mma(
    const __nv_bfloat16* __restrict__ Ah, const __nv_bfloat16* __restrict__ Al,
    const __nv_bfloat16* __restrict__ Bh, const __nv_bfloat16* __restrict__ Bl,
    const float* __restrict__ bias, float* __restrict__ C,
    int M, int N, int K)
{
    extern __shared__ char sm[];
    const uint32_t smem = smem_u32(sm);
    const int tid = threadIdx.x;
    const int wid = tid >> 5, lane = tid & 31;
    const int wr = wid >> 2, wc = wid & 3;          // warp tile: rows wr*64, cols wc*32
    const int bm = blockIdx.y * 128, bn = blockIdx.x * 128;

    const __nv_bfloat16* srcs[4] = {
        Ah + (size_t)bm * K, Al + (size_t)bm * K,
        Bh + (size_t)bn * K, Bl + (size_t)bn * K };

    float acc[4][4][4];                              // [mt][nt][4]
#pragma unroll
    for (int mt = 0; mt < 4; mt++)
#pragma unroll
        for (int nt = 0; nt < 4; nt++)
#pragma unroll
            for (int e = 0; e < 4; e++) acc[mt][nt][e] = 0.f;

    const int nch = K >> 5;                          // K/32

    auto issue = [&](int c) {
        const int k0 = c << 5;
        const uint32_t bofs = smem + (c & 1) * BUF_SB;
#pragma unroll
        for (int t = 0; t < 4; t++) {
            const __nv_bfloat16* sp = srcs[t];
#pragma unroll
            for (int i = 0; i < 2; i++) {
                int lin = tid + i * 256;
                int row = lin >> 2, g = lin & 3;
                cp16(bofs + (uint32_t)(t * TILE_SB + row * APITCH + g * 16),
                     sp + (size_t)row * K + k0 + g * 8);
            }
        }
        asm volatile("cp.async.commit_group;" ::: "memory");
    };

    issue(0);
    for (int c = 0; c < nch; ++c) {
        if (c + 1 < nch) {
            issue(c + 1);
            asm volatile("cp.async.wait_group 1;" ::: "memory");
        } else {
            asm volatile("cp.async.wait_group 0;" ::: "memory");
        }
        __syncthreads();

        const uint32_t bofs = smem + (c & 1) * BUF_SB;
        const uint32_t A_h = bofs;
        const uint32_t A_l = bofs + TILE_SB;
        const uint32_t B_h = bofs + 2 * TILE_SB;
        const uint32_t B_l = bofs + 3 * TILE_SB;
        // ldmatrix lane addressing
        const int ar = wr * 64 + (lane & 15);        // A row
        const int acg = (lane >> 4) & 1;             // A 16B col group
        const int br = wc * 32 + (lane & 7);         // B row (n)
        const int bcg = (lane >> 3) & 1;             // B 16B col group

#pragma unroll
        for (int s = 0; s < 2; s++) {                // two k16 steps
            const uint32_t akoff = s * 32 + acg * 16;
            const uint32_t bkoff = s * 32 + bcg * 16;
            uint32_t ah[4][4], al[4][4], bh[4][2], bl[4][2];
#pragma unroll
            for (int mt = 0; mt < 4; mt++) {
                uint32_t rb = (uint32_t)((ar + mt * 16) * APITCH) + akoff;
                ldsm_x4(ah[mt], A_h + rb);
                ldsm_x4(al[mt], A_l + rb);
            }
#pragma unroll
            for (int nt = 0; nt < 4; nt++) {
                uint32_t rb = (uint32_t)((br + nt * 8) * APITCH) + bkoff;
                ldsm_x2(bh[nt], B_h + rb);
                ldsm_x2(bl[nt], B_l + rb);
            }
#pragma unroll
            for (int mt = 0; mt < 4; mt++)
#pragma unroll
                for (int nt = 0; nt < 4; nt++) {
                    mma16816(acc[mt][nt], ah[mt], bh[nt]);
                    mma16816(acc[mt][nt], ah[mt], bl[nt]);
                    mma16816(acc[mt][nt], al[mt], bh[nt]);
                }
        }
        __syncthreads();
    }

    // epilogue: d layout m16n8: {c0,c1}: row lane>>2, cols (lane&3)*2+{0,1};
    //           {c2,c3}: row (lane>>2)+8
    const int r0 = lane >> 2, c0 = (lane & 3) * 2;
#pragma unroll
    for (int mt = 0; mt < 4; mt++) {
#pragma unroll
        for (int nt = 0; nt < 4; nt++) {
            int col = bn + wc * 32 + nt * 8 + c0;
            float b0 = bias[col], b1 = bias[col + 1];
            int row = bm + wr * 64 + mt * 16 + r0;
            float2 v0 = make_float2(acc[mt][nt][0] + b0, acc[mt][nt][1] + b1);
            float2 v1 = make_float2(acc[mt][nt][2] + b0, acc[mt][nt][3] + b1);
            *(float2*)&C[(size_t)row * N + col] = v0;
            *(float2*)&C[(size_t)(row + 8) * N + col] = v1;
        }
    }
}

// ---------------------------------------------------------------------------
// Head-0 selection scores: S[b,i,j] = (1<=j<i) ? max(0, 0.125*q0[i].k0[j]) : 0
// ---------------------------------------------------------------------------
__global__ __launch_bounds__(256) void score0_kernel()
{
    const int jt = blockIdx.x, it = blockIdx.y, b = blockIdx.z;
    const int tid = threadIdx.x;
    const int ty = tid >> 4, tx = tid & 15;

    if (jt > it) {
        float4 z = make_float4(0.f, 0.f, 0.f, 0.f);
#pragma unroll
        for (int l = 0; l < 4; l++) {
            int lin = tid + l * 256;
            int r = lin >> 4, cg = (lin & 15) << 2;
            *(float4*)&g_S[((size_t)(b * NT) + it * 64 + r) * NT + jt * 64 + cg] = z;
        }
        return;
    }

    __shared__ float qts[64 * 68];
    __shared__ float kts[64 * 68];
    const float* qb = g_qkv + ((size_t)(b * NT) + it * 64) * QKVW;
    const float* kb = g_qkv + ((size_t)(b * NT) + jt * 64) * QKVW + 768;
#pragma unroll
    for (int l = 0; l < 4; l++) {
        int lin = tid + l * 256;
        int r = lin >> 4, dg = (lin & 15) << 2;
        float4 qv = *(const float4*)&qb[(size_t)r * QKVW + dg];
        qts[(dg + 0) * 68 + r] = qv.x; qts[(dg + 1) * 68 + r] = qv.y;
        qts[(dg + 2) * 68 + r] = qv.z; qts[(dg + 3) * 68 + r] = qv.w;
        float4 kv = *(const float4*)&kb[(size_t)r * QKVW + dg];
        kts[(dg + 0) * 68 + r] = kv.x; kts[(dg + 1) * 68 + r] = kv.y;
        kts[(dg + 2) * 68 + r] = kv.z; kts[(dg + 3) * 68 + r] = kv.w;
    }
    __syncthreads();

    float s[4][4];
#pragma unroll
    for (int r = 0; r < 4; r++)
#pragma unroll
        for (int c = 0; c < 4; c++) s[r][c] = 0.f;

#pragma unroll 16
    for (int d = 0; d < 64; d++) {
        float4 qa = *(const float4*)&qts[d * 68 + ty * 4];
        float4 ka = *(const float4*)&kts[d * 68 + tx * 4];
        float qr[4] = {qa.x, qa.y, qa.z, qa.w};
        float kr[4] = {ka.x, ka.y, ka.z, ka.w};
#pragma unroll
        for (int r = 0; r < 4; r++)
#pragma unroll
            for (int c = 0; c < 4; c++) s[r][c] += qr[r] * kr[c];
    }

#pragma unroll
    for (int r = 0; r < 4; r++) {
        int i = it * 64 + ty * 4 + r;
        float o[4];
#pragma unroll
        for (int c = 0; c < 4; c++) {
            int j = jt * 64 + tx * 4 + c;
            float v = s[r][c] * 0.125f;
            o[c] = (j >= 1 && j < i) ? fmaxf(v, 0.f) : 0.f;
        }
        *(float4*)&g_S[((size_t)(b * NT) + i) * NT + jt * 64 + tx * 4] =
            make_float4(o[0], o[1], o[2], o[3]);
    }
}

// ---------------------------------------------------------------------------
// Column scan:  F[b,i,j] = sum_{i'<i} S[b,i',j]
// ---------------------------------------------------------------------------
__global__ __launch_bounds__(256) void colsum_kernel()
{
    int j = blockIdx.x * 256 + threadIdx.x;
    int b = blockIdx.y >> 6, ch = blockIdx.y & 63;
    const float* p = g_S + ((size_t)(b * NT) + ch * CHROWS) * NT + j;
    float s = 0.f;
    for (int r = 0; r < CHROWS; r++) s += p[(size_t)r * NT];
    g_csum[(b * NCHUNK + ch) * NT + j] = s;
}

__global__ __launch_bounds__(256) void scan_kernel()
{
    int j = blockIdx.x * 256 + threadIdx.x;
    int b = blockIdx.y >> 6, ch = blockIdx.y & 63;
    float run = 0.f;
    for (int c = 0; c < ch; c++) run += g_csum[(b * NCHUNK + c) * NT + j];
    size_t base = ((size_t)(b * NT) + ch * CHROWS) * NT + j;
    for (int r = 0; r < CHROWS; r++) {
        size_t idx = base + (size_t)r * NT;
        float sv = g_S[idx];
        g_F[idx] = run;
        run += sv;
    }
}

// ---------------------------------------------------------------------------
// Fused selective attention (flash-style), logits = 0.125*qk - F, causal.
// ---------------------------------------------------------------------------
__global__ __launch_bounds__(256) void attn_kernel()
{
    extern __shared__ float smf[];
    float* qts = smf;
    float* kts = smf + 64 * 68;
    float* vs  = smf + 2 * 64 * 68;

    const int qt = gridDim.x - 1 - blockIdx.x;
    const int h = blockIdx.y, b = blockIdx.z;
    const int tid = threadIdx.x;
    const int ty = tid >> 4, tx = tid & 15;
    const int i0 = qt * 64;

    const float* qb = g_qkv + ((size_t)(b * NT) + i0) * QKVW + h * ND;
#pragma unroll
    for (int l = 0; l < 4; l++) {
        int lin = tid + l * 256;
        int r = lin >> 4, dg = (lin & 15) << 2;
        float4 qv = *(const float4*)&qb[(size_t)r * QKVW + dg];
        qts[(dg + 0) * 68 + r] = qv.x; qts[(dg + 1) * 68 + r] = qv.y;
        qts[(dg + 2) * 68 + r] = qv.z; qts[(dg + 3) * 68 + r] = qv.w;
    }

    float m[4], lsum[4], acc[4][4];
#pragma unroll
    for (int r = 0; r < 4; r++) {
        m[r] = -INFINITY; lsum[r] = 0.f;
#pragma unroll
        for (int c = 0; c < 4; c++) acc[r][c] = 0.f;
    }

    for (int kt = 0; kt <= qt; kt++) {
        __syncthreads();
        const float* kb = g_qkv + ((size_t)(b * NT) + kt * 64) * QKVW + 768 + h * ND;
        const float* vb = kb + 768;
#pragma unroll
        for (int l = 0; l < 4; l++) {
            int lin = tid + l * 256;
            int r = lin >> 4, dg = (lin & 15) << 2;
            float4 kv = *(const float4*)&kb[(size_t)r * QKVW + dg];
            kts[(dg + 0) * 68 + r] = kv.x; kts[(dg + 1) * 68 + r] = kv.y;
            kts[(dg + 2) * 68 + r] = kv.z; kts[(dg + 3) * 68 + r] = kv.w;
            float4 vv = *(const float4*)&vb[(size_t)r * QKVW + dg];
            *(float4*)&vs[r * 68 + dg] = vv;
        }
        __syncthreads();

        float s[4][4];
#pragma unroll
        for (int r = 0; r < 4; r++)
#pragma unroll
            for (int c = 0; c < 4; c++) s[r][c] = 0.f;

#pragma unroll 16
        for (int d = 0; d < 64; d++) {
            float4 qa = *(const float4*)&qts[d * 68 + ty * 4];
            float4 ka = *(const float4*)&kts[d * 68 + tx * 4];
            float qr[4] = {qa.x, qa.y, qa.z, qa.w};
            float kr[4] = {ka.x, ka.y, ka.z, ka.w};
#pragma unroll
            for (int r = 0; r < 4; r++)
#pragma unroll
                for (int c = 0; c < 4; c++) s[r][c] += qr[r] * kr[c];
        }

#pragma unroll
        for (int r = 0; r < 4; r++) {
            int i = i0 + ty * 4 + r;
            float4 fr = *(const float4*)&g_F[((size_t)(b * NT) + i) * NT + kt * 64 + tx * 4];
            float fv[4] = {fr.x, fr.y, fr.z, fr.w};
            float mt = -INFINITY;
#pragma unroll
            for (int c = 0; c < 4; c++) {
                int j = kt * 64 + tx * 4 + c;
                float v = s[r][c] * 0.125f - fv[c];
                if (kt == qt && j > i) v = -INFINITY;
                s[r][c] = v;
                mt = fmaxf(mt, v);
            }
#pragma unroll
            for (int off = 8; off >= 1; off >>= 1)
                mt = fmaxf(mt, __shfl_xor_sync(0xffffffffu, mt, off));
            float mn = fmaxf(m[r], mt);
            float sc = __expf(m[r] - mn);
            float rs = 0.f;
#pragma unroll
            for (int c = 0; c < 4; c++) {
                float p = __expf(s[r][c] - mn);
                s[r][c] = p;
                rs += p;
            }
#pragma unroll
            for (int off = 8; off >= 1; off >>= 1)
                rs += __shfl_xor_sync(0xffffffffu, rs, off);
            lsum[r] = lsum[r] * sc + rs;
            m[r] = mn;
#pragma unroll
            for (int c = 0; c < 4; c++) acc[r][c] *= sc;
        }

        __syncthreads();
#pragma unroll
        for (int c = 0; c < 4; c++)
#pragma unroll
            for (int r = 0; r < 4; r++)
                kts[(tx * 4 + c) * 68 + ty * 4 + r] = s[r][c];
        __syncthreads();

#pragma unroll 16
        for (int kk = 0; kk < 64; kk++) {
            float4 pa = *(const float4*)&kts[kk * 68 + ty * 4];
            float4 va = *(const float4*)&vs[kk * 68 + tx * 4];
            float pr[4] = {pa.x, pa.y, pa.z, pa.w};
            float vr[4] = {va.x, va.y, va.z, va.w};
#pragma unroll
            for (int r = 0; r < 4; r++)
#pragma unroll
                for (int c = 0; c < 4; c++) acc[r][c] += pr[r] * vr[c];
        }
    }

#pragma unroll
    for (int r = 0; r < 4; r++) {
        int i = i0 + ty * 4 + r;
        float inv = 1.0f / lsum[r];
        float4 o = make_float4(acc[r][0] * inv, acc[r][1] * inv,
                               acc[r][2] * inv, acc[r][3] * inv);
        *(float4*)&g_y[((size_t)(b * NT) + i) * (NH * ND) + h * ND + tx * 4] = o;
    }
}

// ---------------------------------------------------------------------------
extern "C" void kernel_launch(void* const* d_in, const int* in_sizes, int n_in,
                              void* d_out, int out_size)
{
    (void)in_sizes; (void)n_in; (void)out_size;
    const float* x      = (const float*)d_in[0];
    const float* w_attn = (const float*)d_in[1];
    const float* b_attn = (const float*)d_in[2];
    const float* w_proj = (const float*)d_in[3];
    const float* b_proj = (const float*)d_in[4];
    float* out = (float*)d_out;

    float *qkv = nullptr, *y = nullptr;
    cudaGetSymbolAddress((void**)&qkv, g_qkv);
    cudaGetSymbolAddress((void**)&y, g_y);
    __nv_bfloat16 *xh, *xl, *wah, *wal, *wph, *wpl, *yh, *yl;
    cudaGetSymbolAddress((void**)&xh, g_xh);   cudaGetSymbolAddress((void**)&xl, g_xl);
    cudaGetSymbolAddress((void**)&wah, g_wah); cudaGetSymbolAddress((void**)&wal, g_wal);
    cudaGetSymbolAddress((void**)&wph, g_wph); cudaGetSymbolAddress((void**)&wpl, g_wpl);
    cudaGetSymbolAddress((void**)&yh, g_yh);   cudaGetSymbolAddress((void**)&yl, g_yl);

    const int attn_smem = 3 * 64 * 68 * 4;
    cudaFuncSetAttribute(attn_kernel,
                         cudaFuncAttributeMaxDynamicSharedMemorySize, attn_smem);
    cudaFuncSetAttribute(gemm_mma,
                         cudaFuncAttributeMaxDynamicSharedMemorySize, GEMM_SMEM);

    // 0) split-bf16 conversions of x, w_attn, w_proj
    {
        int n4x = (NB * NT * NC) / 4;
        convert_hilo<<<(n4x + 255) / 256, 256>>>(x, xh, xl, n4x);
        int n4a = (QKVW * NC) / 4;
        convert_hilo<<<(n4a + 255) / 256, 256>>>(w_attn, wah, wal, n4a);
        int n4p = (NC * NC) / 4;
        convert_hilo<<<(n4p + 255) / 256, 256>>>(w_proj, wph, wpl, n4p);
    }

    // 1) QKV projection (mma.sync split-bf16): [4096,768] x [2304,768]^T -> g_qkv
    gemm_mma<<<dim3(QKVW / 128, (NB * NT) / 128), 256, GEMM_SMEM>>>(
        xh, xl, wah, wal, b_attn, qkv, NB * NT, QKVW, NC);

    // 2) head-0 masked relu scores -> g_S
    score0_kernel<<<dim3(NT / 64, NT / 64, NB), 256>>>();

    // 3) exclusive column cumsum -> g_F
    colsum_kernel<<<dim3(NT / 256, NB * NCHUNK), 256>>>();
    scan_kernel<<<dim3(NT / 256, NB * NCHUNK), 256>>>();

    // 4) fused selective attention -> g_y
    attn_kernel<<<dim3(NT / 64, NH, NB), 256, attn_smem>>>();

    // 5) convert y, output projection: [4096,768] x [768,768]^T -> out
    {
        int n4y = (NB * NT * NC) / 4;
        convert_hilo<<<(n4y + 255) / 256, 256>>>(y, yh, yl, n4y);
    }
    gemm_mma<<<dim3(NC / 128, (NB * NT) / 128), 256, GEMM_SMEM>>>(
        yh, yl, wph, wpl, b_proj, out, NB * NT, NC, NC);
}

// round 13
// speedup vs baseline: 2.1321x; 1.5670x over previous
#include <cuda_runtime.h>
#include <cuda_bf16.h>
#include <math.h>
#include <stdint.h>

#define NB 2
#define NT 2048
#define NC 768
#define NH 12
#define ND 64
#define QKVW 2304
#define NCHUNK 64
#define CHROWS 32

// ---------------- scratch (device globals; no allocation allowed) ----------
__device__ __align__(256) float g_qkv[(size_t)NB * NT * QKVW];
__device__ __align__(256) float g_S[(size_t)NB * NT * NT];
__device__ __align__(256) float g_F[(size_t)NB * NT * NT];
__device__ __align__(256) float g_csum[NB * NCHUNK * NT];
__device__ __align__(256) float g_y[(size_t)NB * NT * (NH * ND)];
// split-bf16 copies
__device__ __align__(256) __nv_bfloat16 g_xh[(size_t)NB * NT * NC];
__device__ __align__(256) __nv_bfloat16 g_xl[(size_t)NB * NT * NC];
__device__ __align__(256) __nv_bfloat16 g_wah[(size_t)QKVW * NC];
__device__ __align__(256) __nv_bfloat16 g_wal[(size_t)QKVW * NC];
__device__ __align__(256) __nv_bfloat16 g_wph[(size_t)NC * NC];
__device__ __align__(256) __nv_bfloat16 g_wpl[(size_t)NC * NC];
__device__ __align__(256) __nv_bfloat16 g_yh[(size_t)NB * NT * NC];
__device__ __align__(256) __nv_bfloat16 g_yl[(size_t)NB * NT * NC];

// =========================== warp-MMA helpers (sm_80+ PTX) =================
__device__ __forceinline__ uint32_t smem_u32(const void* p) {
    uint32_t a;
    asm("{ .reg .u64 t; cvta.to.shared.u64 t, %1; cvt.u32.u64 %0, t; }" : "=r"(a) : "l"(p));
    return a;
}
__device__ __forceinline__ void mma16816(float* d, const uint32_t* a, const uint32_t* b) {
    asm volatile("mma.sync.aligned.m16n8k16.row.col.f32.bf16.bf16.f32 "
        "{%0,%1,%2,%3}, {%4,%5,%6,%7}, {%8,%9}, {%0,%1,%2,%3};"
        : "+f"(d[0]), "+f"(d[1]), "+f"(d[2]), "+f"(d[3])
        : "r"(a[0]), "r"(a[1]), "r"(a[2]), "r"(a[3]), "r"(b[0]), "r"(b[1]));
}
__device__ __forceinline__ void ldsm_x4(uint32_t* r, uint32_t addr) {
    asm volatile("ldmatrix.sync.aligned.m8n8.x4.shared.b16 {%0,%1,%2,%3}, [%4];"
        : "=r"(r[0]), "=r"(r[1]), "=r"(r[2]), "=r"(r[3]) : "r"(addr));
}
__device__ __forceinline__ void ldsm_x4t(uint32_t* r, uint32_t addr) {
    asm volatile("ldmatrix.sync.aligned.m8n8.x4.trans.shared.b16 {%0,%1,%2,%3}, [%4];"
        : "=r"(r[0]), "=r"(r[1]), "=r"(r[2]), "=r"(r[3]) : "r"(addr));
}
__device__ __forceinline__ void ldsm_x2(uint32_t* r, uint32_t addr) {
    asm volatile("ldmatrix.sync.aligned.m8n8.x2.shared.b16 {%0,%1}, [%2];"
        : "=r"(r[0]), "=r"(r[1]) : "r"(addr));
}
__device__ __forceinline__ void cp16(uint32_t dst, const void* src) {
    asm volatile("cp.async.cg.shared.global [%0], [%1], 16;" :: "r"(dst), "l"(src));
}
__device__ __forceinline__ uint32_t pack_bf16x2(float lo, float hi) {
    uint32_t r;
    asm("cvt.rn.bf16x2.f32 %0, %1, %2;" : "=r"(r) : "f"(hi), "f"(lo));
    return r;
}
__device__ __forceinline__ float bf16lo_f(uint32_t p) { return __uint_as_float(p << 16); }
__device__ __forceinline__ float bf16hi_f(uint32_t p) { return __uint_as_float(p & 0xffff0000u); }
__device__ __forceinline__ float ex2f(float x) {
    float r; asm("ex2.approx.f32 %0, %1;" : "=f"(r) : "f"(x)); return r;
}
// store 4 fp32 as hi/lo bf16 quads (8 bytes each) to shared
__device__ __forceinline__ void sthilo4(uint32_t dh, uint32_t dl, float4 v) {
    uint32_t h0 = pack_bf16x2(v.x, v.y);
    uint32_t h1 = pack_bf16x2(v.z, v.w);
    float lx = v.x - bf16lo_f(h0), ly = v.y - bf16hi_f(h0);
    float lz = v.z - bf16lo_f(h1), lw = v.w - bf16hi_f(h1);
    uint32_t l0 = pack_bf16x2(lx, ly), l1 = pack_bf16x2(lz, lw);
    asm volatile("st.shared.v2.b32 [%0], {%1, %2};" :: "r"(dh), "r"(h0), "r"(h1));
    asm volatile("st.shared.v2.b32 [%0], {%1, %2};" :: "r"(dl), "r"(l0), "r"(l1));
}

// ---------------------------------------------------------------------------
// convert fp32 -> (hi bf16, lo bf16)
// ---------------------------------------------------------------------------
__global__ __launch_bounds__(256) void convert_hilo(
    const float* __restrict__ src, __nv_bfloat16* __restrict__ h,
    __nv_bfloat16* __restrict__ l, int n4)
{
    int i = blockIdx.x * 256 + threadIdx.x;
    if (i >= n4) return;
    float4 v = ((const float4*)src)[i];
    float vs[4] = {v.x, v.y, v.z, v.w};
    uint32_t hb[4], lb[4];
#pragma unroll
    for (int c = 0; c < 4; c++) {
        __nv_bfloat16 hh = __float2bfloat16(vs[c]);
        __nv_bfloat16 ll = __float2bfloat16(vs[c] - __bfloat162float(hh));
        hb[c] = __bfloat16_as_ushort(hh);
        lb[c] = __bfloat16_as_ushort(ll);
    }
    uint2 ho, lo;
    ho.x = hb[0] | (hb[1] << 16); ho.y = hb[2] | (hb[3] << 16);
    lo.x = lb[0] | (lb[1] << 16); lo.y = lb[2] | (lb[3] << 16);
    *(uint2*)(h + (size_t)i * 4) = ho;
    *(uint2*)(l + (size_t)i * 4) = lo;
}

// ---------------------------------------------------------------------------
// split-bf16 GEMM-NT + bias via mma.sync (unchanged from R11, passing)
// ---------------------------------------------------------------------------
#define APITCH 80
#define TILE_SB (128 * APITCH)
#define BUF_SB  (4 * TILE_SB)
#define GEMM_SMEM (2 * BUF_SB)

__global__ __launch_bounds__(256) void gemm_mma(
    const __nv_bfloat16* __restrict__ Ah, const __nv_bfloat16* __restrict__ Al,
    const __nv_bfloat16* __restrict__ Bh, const __nv_bfloat16* __restrict__ Bl,
    const float* __restrict__ bias, float* __restrict__ C,
    int M, int N, int K)
{
    extern __shared__ char sm[];
    const uint32_t smem = smem_u32(sm);
    const int tid = threadIdx.x;
    const int wid = tid >> 5, lane = tid & 31;
    const int wr = wid >> 2, wc = wid & 3;
    const int bm = blockIdx.y * 128, bn = blockIdx.x * 128;

    const __nv_bfloat16* srcs[4] = {
        Ah + (size_t)bm * K, Al + (size_t)bm * K,
        Bh + (size_t)bn * K, Bl + (size_t)bn * K };

    float acc[4][4][4];
#pragma unroll
    for (int mt = 0; mt < 4; mt++)
#pragma unroll
        for (int nt = 0; nt < 4; nt++)
#pragma unroll
            for (int e = 0; e < 4; e++) acc[mt][nt][e] = 0.f;

    const int nch = K >> 5;

    auto issue = [&](int c) {
        const int k0 = c << 5;
        const uint32_t bofs = smem + (c & 1) * BUF_SB;
#pragma unroll
        for (int t = 0; t < 4; t++) {
            const __nv_bfloat16* sp = srcs[t];
#pragma unroll
            for (int i = 0; i < 2; i++) {
                int lin = tid + i * 256;
                int row = lin >> 2, g = lin & 3;
                cp16(bofs + (uint32_t)(t * TILE_SB + row * APITCH + g * 16),
                     sp + (size_t)row * K + k0 + g * 8);
            }
        }
        asm volatile("cp.async.commit_group;" ::: "memory");
    };

    issue(0);
    for (int c = 0; c < nch; ++c) {
        if (c + 1 < nch) {
            issue(c + 1);
            asm volatile("cp.async.wait_group 1;" ::: "memory");
        } else {
            asm volatile("cp.async.wait_group 0;" ::: "memory");
        }
        __syncthreads();

        const uint32_t bofs = smem + (c & 1) * BUF_SB;
        const uint32_t A_h = bofs;
        const uint32_t A_l = bofs + TILE_SB;
        const uint32_t B_h = bofs + 2 * TILE_SB;
        const uint32_t B_l = bofs + 3 * TILE_SB;
        const int ar = wr * 64 + (lane & 15);
        const int acg = (lane >> 4) & 1;
        const int br = wc * 32 + (lane & 7);
        const int bcg = (lane >> 3) & 1;

#pragma unroll
        for (int s = 0; s < 2; s++) {
            const uint32_t akoff = s * 32 + acg * 16;
            const uint32_t bkoff = s * 32 + bcg * 16;
            uint32_t ah[4][4], al[4][4], bh[4][2], bl[4][2];
#pragma unroll
            for (int mt = 0; mt < 4; mt++) {
                uint32_t rb = (uint32_t)((ar + mt * 16) * APITCH) + akoff;
                ldsm_x4(ah[mt], A_h + rb);
                ldsm_x4(al[mt], A_l + rb);
            }
#pragma unroll
            for (int nt = 0; nt < 4; nt++) {
                uint32_t rb = (uint32_t)((br + nt * 8) * APITCH) + bkoff;
                ldsm_x2(bh[nt], B_h + rb);
                ldsm_x2(bl[nt], B_l + rb);
            }
#pragma unroll
            for (int mt = 0; mt < 4; mt++)
#pragma unroll
                for (int nt = 0; nt < 4; nt++) {
                    mma16816(acc[mt][nt], ah[mt], bh[nt]);
                    mma16816(acc[mt][nt], ah[mt], bl[nt]);
                    mma16816(acc[mt][nt], al[mt], bh[nt]);
                }
        }
        __syncthreads();
    }

    const int r0 = lane >> 2, c0 = (lane & 3) * 2;
#pragma unroll
    for (int mt = 0; mt < 4; mt++) {
#pragma unroll
        for (int nt = 0; nt < 4; nt++) {
            int col = bn + wc * 32 + nt * 8 + c0;
            float b0 = bias[col], b1 = bias[col + 1];
            int row = bm + wr * 64 + mt * 16 + r0;
            float2 v0 = make_float2(acc[mt][nt][0] + b0, acc[mt][nt][1] + b1);
            float2 v1 = make_float2(acc[mt][nt][2] + b0, acc[mt][nt][3] + b1);
            *(float2*)&C[(size_t)row * N + col] = v0;
            *(float2*)&C[(size_t)(row + 8) * N + col] = v1;
        }
    }
}

// ---------------------------------------------------------------------------
// Head-0 selection scores: S[b,i,j] = (1<=j<i) ? max(0, 0.125*q0[i].k0[j]) : 0
// ---------------------------------------------------------------------------
__global__ __launch_bounds__(256) void score0_kernel()
{
    const int jt = blockIdx.x, it = blockIdx.y, b = blockIdx.z;
    const int tid = threadIdx.x;
    const int ty = tid >> 4, tx = tid & 15;

    if (jt > it) {
        float4 z = make_float4(0.f, 0.f, 0.f, 0.f);
#pragma unroll
        for (int l = 0; l < 4; l++) {
            int lin = tid + l * 256;
            int r = lin >> 4, cg = (lin & 15) << 2;
            *(float4*)&g_S[((size_t)(b * NT) + it * 64 + r) * NT + jt * 64 + cg] = z;
        }
        return;
    }

    __shared__ float qts[64 * 68];
    __shared__ float kts[64 * 68];
    const float* qb = g_qkv + ((size_t)(b * NT) + it * 64) * QKVW;
    const float* kb = g_qkv + ((size_t)(b * NT) + jt * 64) * QKVW + 768;
#pragma unroll
    for (int l = 0; l < 4; l++) {
        int lin = tid + l * 256;
        int r = lin >> 4, dg = (lin & 15) << 2;
        float4 qv = *(const float4*)&qb[(size_t)r * QKVW + dg];
        qts[(dg + 0) * 68 + r] = qv.x; qts[(dg + 1) * 68 + r] = qv.y;
        qts[(dg + 2) * 68 + r] = qv.z; qts[(dg + 3) * 68 + r] = qv.w;
        float4 kv = *(const float4*)&kb[(size_t)r * QKVW + dg];
        kts[(dg + 0) * 68 + r] = kv.x; kts[(dg + 1) * 68 + r] = kv.y;
        kts[(dg + 2) * 68 + r] = kv.z; kts[(dg + 3) * 68 + r] = kv.w;
    }
    __syncthreads();

    float s[4][4];
#pragma unroll
    for (int r = 0; r < 4; r++)
#pragma unroll
        for (int c = 0; c < 4; c++) s[r][c] = 0.f;

#pragma unroll 16
    for (int d = 0; d < 64; d++) {
        float4 qa = *(const float4*)&qts[d * 68 + ty * 4];
        float4 ka = *(const float4*)&kts[d * 68 + tx * 4];
        float qr[4] = {qa.x, qa.y, qa.z, qa.w};
        float kr[4] = {ka.x, ka.y, ka.z, ka.w};
#pragma unroll
        for (int r = 0; r < 4; r++)
#pragma unroll
            for (int c = 0; c < 4; c++) s[r][c] += qr[r] * kr[c];
    }

#pragma unroll
    for (int r = 0; r < 4; r++) {
        int i = it * 64 + ty * 4 + r;
        float o[4];
#pragma unroll
        for (int c = 0; c < 4; c++) {
            int j = jt * 64 + tx * 4 + c;
            float v = s[r][c] * 0.125f;
            o[c] = (j >= 1 && j < i) ? fmaxf(v, 0.f) : 0.f;
        }
        *(float4*)&g_S[((size_t)(b * NT) + i) * NT + jt * 64 + tx * 4] =
            make_float4(o[0], o[1], o[2], o[3]);
    }
}

// ---------------------------------------------------------------------------
// Column scan:  F[b,i,j] = sum_{i'<i} S[b,i',j]
// ---------------------------------------------------------------------------
__global__ __launch_bounds__(256) void colsum_kernel()
{
    int j = blockIdx.x * 256 + threadIdx.x;
    int b = blockIdx.y >> 6, ch = blockIdx.y & 63;
    const float* p = g_S + ((size_t)(b * NT) + ch * CHROWS) * NT + j;
    float s = 0.f;
    for (int r = 0; r < CHROWS; r++) s += p[(size_t)r * NT];
    g_csum[(b * NCHUNK + ch) * NT + j] = s;
}

__global__ __launch_bounds__(256) void scan_kernel()
{
    int j = blockIdx.x * 256 + threadIdx.x;
    int b = blockIdx.y >> 6, ch = blockIdx.y & 63;
    float run = 0.f;
    for (int c = 0; c < ch; c++) run += g_csum[(b * NCHUNK + c) * NT + j];
    size_t base = ((size_t)(b * NT) + ch * CHROWS) * NT + j;
    for (int r = 0; r < CHROWS; r++) {
        size_t idx = base + (size_t)r * NT;
        float sv = g_S[idx];
        g_F[idx] = run;
        run += sv;
    }
}

// ---------------------------------------------------------------------------
// MMA flash attention: per CTA (b, h, 128 q-rows), 8 warps x 16 rows.
// logits*log2e tracked; S = QK^T and y = PV both 3-pass split-bf16.
// Q A-fragments cached in registers; P converted reg->reg (FA-2 pattern).
// ---------------------------------------------------------------------------
#define AT_PITCH 144
#define ATT_SMEM (512 * AT_PITCH)   // qh,ql(128) kh,kl(64) vh,vl(64) rows

__global__ __launch_bounds__(256, 1) void attn_mma()
{
    extern __shared__ char smc[];
    const uint32_t s_qh = smem_u32(smc);
    const uint32_t s_ql = s_qh + 128 * AT_PITCH;
    const uint32_t s_kh = s_ql + 128 * AT_PITCH;
    const uint32_t s_kl = s_kh + 64 * AT_PITCH;
    const uint32_t s_vh = s_kl + 64 * AT_PITCH;
    const uint32_t s_vl = s_vh + 64 * AT_PITCH;

    const int qi = gridDim.x - 1 - blockIdx.x;     // heavy tiles first
    const int h = blockIdx.y, b = blockIdx.z;
    const int tid = threadIdx.x;
    const int w = tid >> 5, lane = tid & 31;
    const int g = lane >> 2, t4 = lane & 3;
    const int i0 = qi * 128;

    const float SCL = 0.125f * 1.44269504f;        // 0.125 * log2(e)
    const float FL2 = 1.44269504f;

    // ---- load Q tile -> split-bf16 smem ----
    {
        int row = tid >> 1;
        int dg = (tid & 1) * 32;
        const float* qb = g_qkv + ((size_t)(b * NT) + i0 + row) * QKVW + h * 64 + dg;
        uint32_t dh = s_qh + row * AT_PITCH + dg * 2;
        uint32_t dl = s_ql + row * AT_PITCH + dg * 2;
#pragma unroll
        for (int u = 0; u < 8; u++)
            sthilo4(dh + u * 8, dl + u * 8, ((const float4*)qb)[u]);
    }
    __syncthreads();

    // ---- Q A-fragments (persistent registers) ----
    uint32_t qfh[4][4], qfl[4][4];
    {
        uint32_t qrb = (uint32_t)((w * 16 + (lane & 15)) * AT_PITCH) + ((lane >> 4) & 1) * 16;
#pragma unroll
        for (int s = 0; s < 4; s++) {
            ldsm_x4(qfh[s], s_qh + qrb + s * 32);
            ldsm_x4(qfl[s], s_ql + qrb + s * 32);
        }
    }

    float yacc[8][4];
#pragma unroll
    for (int nt = 0; nt < 8; nt++)
#pragma unroll
        for (int e = 0; e < 4; e++) yacc[nt][e] = 0.f;
    float m0 = -INFINITY, m1 = -INFINITY, ls0 = 0.f, ls1 = 0.f;

    const int i_r0 = i0 + w * 16 + g;
    const int i_r1 = i_r0 + 8;
    const int ktend = 2 * qi + 2;

    // lane patterns for batched ldsm_x4
    const int rl = lane & 7, s8 = (lane >> 3) & 1, s16 = lane >> 4;

    for (int kt = 0; kt < ktend; kt++) {
        __syncthreads();
        // ---- load K,V tile -> split-bf16 smem ----
        {
            int kk = tid >> 2;
            int dg = (tid & 3) * 16;
            const float* kb = g_qkv + ((size_t)(b * NT) + kt * 64 + kk) * QKVW + 768 + h * 64 + dg;
            const float* vb = kb + 768;
            uint32_t kh_d = s_kh + kk * AT_PITCH + dg * 2;
            uint32_t kl_d = s_kl + kk * AT_PITCH + dg * 2;
            uint32_t vh_d = s_vh + kk * AT_PITCH + dg * 2;
            uint32_t vl_d = s_vl + kk * AT_PITCH + dg * 2;
#pragma unroll
            for (int u = 0; u < 4; u++) {
                sthilo4(kh_d + u * 8, kl_d + u * 8, ((const float4*)kb)[u]);
                sthilo4(vh_d + u * 8, vl_d + u * 8, ((const float4*)vb)[u]);
            }
        }
        __syncthreads();

        // ---- S = Q K^T (3-pass split) ----
        float sa[8][4];
#pragma unroll
        for (int nt = 0; nt < 8; nt++)
#pragma unroll
            for (int e = 0; e < 4; e++) sa[nt][e] = 0.f;

#pragma unroll
        for (int s = 0; s < 4; s++) {
#pragma unroll
            for (int p = 0; p < 4; p++) {
                uint32_t addr = (uint32_t)(((2 * p + s16) * 8 + rl) * AT_PITCH) + s * 32 + s8 * 16;
                uint32_t bh[4], bl[4];
                ldsm_x4(bh, s_kh + addr);
                ldsm_x4(bl, s_kl + addr);
                mma16816(sa[2 * p],     qfh[s], &bh[0]);
                mma16816(sa[2 * p],     qfh[s], &bl[0]);
                mma16816(sa[2 * p],     qfl[s], &bh[0]);
                mma16816(sa[2 * p + 1], qfh[s], &bh[2]);
                mma16816(sa[2 * p + 1], qfh[s], &bl[2]);
                mma16816(sa[2 * p + 1], qfl[s], &bh[2]);
            }
        }

        // ---- softmax (base-2 domain), logits = sa*SCL - F*FL2 ----
        const float* F0 = g_F + ((size_t)(b * NT) + i_r0) * NT + kt * 64 + 2 * t4;
        const float* F1 = F0 + (size_t)8 * NT;
        const bool edge = (kt >= 2 * qi);
        const int jb = kt * 64 + 2 * t4;
        float mt0 = -INFINITY, mt1 = -INFINITY;
#pragma unroll
        for (int nt = 0; nt < 8; nt++) {
            float2 f0 = *(const float2*)(F0 + nt * 8);
            float2 f1 = *(const float2*)(F1 + nt * 8);
            float v0 = sa[nt][0] * SCL - f0.x * FL2;
            float v1 = sa[nt][1] * SCL - f0.y * FL2;
            float v2 = sa[nt][2] * SCL - f1.x * FL2;
            float v3 = sa[nt][3] * SCL - f1.y * FL2;
            if (edge) {
                int j0 = jb + nt * 8;
                if (j0 > i_r0) v0 = -INFINITY;
                if (j0 + 1 > i_r0) v1 = -INFINITY;
                if (j0 > i_r1) v2 = -INFINITY;
                if (j0 + 1 > i_r1) v3 = -INFINITY;
            }
            sa[nt][0] = v0; sa[nt][1] = v1; sa[nt][2] = v2; sa[nt][3] = v3;
            mt0 = fmaxf(mt0, fmaxf(v0, v1));
            mt1 = fmaxf(mt1, fmaxf(v2, v3));
        }
        mt0 = fmaxf(mt0, __shfl_xor_sync(0xffffffffu, mt0, 1));
        mt0 = fmaxf(mt0, __shfl_xor_sync(0xffffffffu, mt0, 2));
        mt1 = fmaxf(mt1, __shfl_xor_sync(0xffffffffu, mt1, 1));
        mt1 = fmaxf(mt1, __shfl_xor_sync(0xffffffffu, mt1, 2));
        float mn0 = fmaxf(m0, mt0), mn1 = fmaxf(m1, mt1);
        float sc0 = ex2f(m0 - mn0), sc1 = ex2f(m1 - mn1);
        m0 = mn0; m1 = mn1;

        uint32_t pfh01[8], pfh23[8], pfl01[8], pfl23[8];
        float rs0 = 0.f, rs1 = 0.f;
#pragma unroll
        for (int nt = 0; nt < 8; nt++) {
            float p0 = ex2f(sa[nt][0] - m0);
            float p1 = ex2f(sa[nt][1] - m0);
            float p2 = ex2f(sa[nt][2] - m1);
            float p3 = ex2f(sa[nt][3] - m1);
            rs0 += p0 + p1; rs1 += p2 + p3;
            uint32_t h01 = pack_bf16x2(p0, p1);
            uint32_t h23 = pack_bf16x2(p2, p3);
            pfh01[nt] = h01; pfh23[nt] = h23;
            pfl01[nt] = pack_bf16x2(p0 - bf16lo_f(h01), p1 - bf16hi_f(h01));
            pfl23[nt] = pack_bf16x2(p2 - bf16lo_f(h23), p3 - bf16hi_f(h23));
        }
        ls0 = ls0 * sc0 + rs0;
        ls1 = ls1 * sc1 + rs1;
#pragma unroll
        for (int nt = 0; nt < 8; nt++) {
            yacc[nt][0] *= sc0; yacc[nt][1] *= sc0;
            yacc[nt][2] *= sc1; yacc[nt][3] *= sc1;
        }

        // ---- y += P V (3-pass split), V via ldsm trans ----
#pragma unroll
        for (int s = 0; s < 4; s++) {
            uint32_t ah[4] = { pfh01[2 * s], pfh23[2 * s], pfh01[2 * s + 1], pfh23[2 * s + 1] };
            uint32_t al[4] = { pfl01[2 * s], pfl23[2 * s], pfl01[2 * s + 1], pfl23[2 * s + 1] };
#pragma unroll
            for (int p = 0; p < 4; p++) {
                uint32_t addr = (uint32_t)((16 * s + s8 * 8 + rl) * AT_PITCH) + (2 * p + s16) * 16;
                uint32_t vh[4], vl[4];
                ldsm_x4t(vh, s_vh + addr);
                ldsm_x4t(vl, s_vl + addr);
                mma16816(yacc[2 * p],     ah, &vh[0]);
                mma16816(yacc[2 * p],     ah, &vl[0]);
                mma16816(yacc[2 * p],     al, &vh[0]);
                mma16816(yacc[2 * p + 1], ah, &vh[2]);
                mma16816(yacc[2 * p + 1], ah, &vl[2]);
                mma16816(yacc[2 * p + 1], al, &vh[2]);
            }
        }
    }

    // ---- finalize ----
    ls0 += __shfl_xor_sync(0xffffffffu, ls0, 1);
    ls0 += __shfl_xor_sync(0xffffffffu, ls0, 2);
    ls1 += __shfl_xor_sync(0xffffffffu, ls1, 1);
    ls1 += __shfl_xor_sync(0xffffffffu, ls1, 2);
    float inv0 = 1.0f / ls0, inv1 = 1.0f / ls1;
    float* y0 = g_y + ((size_t)(b * NT) + i_r0) * (NH * ND) + h * 64 + 2 * t4;
    float* y1 = g_y + ((size_t)(b * NT) + i_r1) * (NH * ND) + h * 64 + 2 * t4;
#pragma unroll
    for (int nt = 0; nt < 8; nt++) {
        *(float2*)(y0 + nt * 8) = make_float2(yacc[nt][0] * inv0, yacc[nt][1] * inv0);
        *(float2*)(y1 + nt * 8) = make_float2(yacc[nt][2] * inv1, yacc[nt][3] * inv1);
    }
}

// ---------------------------------------------------------------------------
extern "C" void kernel_launch(void* const* d_in, const int* in_sizes, int n_in,
                              void* d_out, int out_size)
{
    (void)in_sizes; (void)n_in; (void)out_size;
    const float* x      = (const float*)d_in[0];
    const float* w_attn = (const float*)d_in[1];
    const float* b_attn = (const float*)d_in[2];
    const float* w_proj = (const float*)d_in[3];
    const float* b_proj = (const float*)d_in[4];
    float* out = (float*)d_out;

    float *qkv = nullptr, *y = nullptr;
    cudaGetSymbolAddress((void**)&qkv, g_qkv);
    cudaGetSymbolAddress((void**)&y, g_y);
    __nv_bfloat16 *xh, *xl, *wah, *wal, *wph, *wpl, *yh, *yl;
    cudaGetSymbolAddress((void**)&xh, g_xh);   cudaGetSymbolAddress((void**)&xl, g_xl);
    cudaGetSymbolAddress((void**)&wah, g_wah); cudaGetSymbolAddress((void**)&wal, g_wal);
    cudaGetSymbolAddress((void**)&wph, g_wph); cudaGetSymbolAddress((void**)&wpl, g_wpl);
    cudaGetSymbolAddress((void**)&yh, g_yh);   cudaGetSymbolAddress((void**)&yl, g_yl);

    cudaFuncSetAttribute(gemm_mma,
                         cudaFuncAttributeMaxDynamicSharedMemorySize, GEMM_SMEM);
    cudaFuncSetAttribute(attn_mma,
                         cudaFuncAttributeMaxDynamicSharedMemorySize, ATT_SMEM);

    // 0) split-bf16 conversions of x, w_attn, w_proj
    {
        int n4x = (NB * NT * NC) / 4;
        convert_hilo<<<(n4x + 255) / 256, 256>>>(x, xh, xl, n4x);
        int n4a = (QKVW * NC) / 4;
        convert_hilo<<<(n4a + 255) / 256, 256>>>(w_attn, wah, wal, n4a);
        int n4p = (NC * NC) / 4;
        convert_hilo<<<(n4p + 255) / 256, 256>>>(w_proj, wph, wpl, n4p);
    }

    // 1) QKV projection: [4096,768] x [2304,768]^T -> g_qkv
    gemm_mma<<<dim3(QKVW / 128, (NB * NT) / 128), 256, GEMM_SMEM>>>(
        xh, xl, wah, wal, b_attn, qkv, NB * NT, QKVW, NC);

    // 2) head-0 masked relu scores -> g_S
    score0_kernel<<<dim3(NT / 64, NT / 64, NB), 256>>>();

    // 3) exclusive column cumsum -> g_F
    colsum_kernel<<<dim3(NT / 256, NB * NCHUNK), 256>>>();
    scan_kernel<<<dim3(NT / 256, NB * NCHUNK), 256>>>();

    // 4) MMA flash attention -> g_y
    attn_mma<<<dim3(NT / 128, NH, NB), 256, ATT_SMEM>>>();

    // 5) convert y, output projection: [4096,768] x [768,768]^T -> out
    {
        int n4y = (NB * NT * NC) / 4;
        convert_hilo<<<(n4y + 255) / 256, 256>>>(y, yh, yl, n4y);
    }
    gemm_mma<<<dim3(NC / 128, (NB * NT) / 128), 256, GEMM_SMEM>>>(
        yh, yl, wph, wpl, b_proj, out, NB * NT, NC, NC);
}

// round 14
// speedup vs baseline: 2.5218x; 1.1828x over previous
#include <cuda_runtime.h>
#include <cuda_bf16.h>
#include <math.h>
#include <stdint.h>

#define NB 2
#define NT 2048
#define NC 768
#define NH 12
#define ND 64
#define QKVW 2304
#define NCHUNK 64
#define CHROWS 32

// ---------------- scratch (device globals; no allocation allowed) ----------
__device__ __align__(256) float g_qkv[(size_t)NB * NT * QKVW];
__device__ __align__(256) float g_S[(size_t)NB * NT * NT];
__device__ __align__(256) float g_F[(size_t)NB * NT * NT];
__device__ __align__(256) float g_csum[NB * NCHUNK * NT];
__device__ __align__(256) float g_y[(size_t)NB * NT * (NH * ND)];
// split-bf16 copies
__device__ __align__(256) __nv_bfloat16 g_xh[(size_t)NB * NT * NC];
__device__ __align__(256) __nv_bfloat16 g_xl[(size_t)NB * NT * NC];
__device__ __align__(256) __nv_bfloat16 g_wah[(size_t)QKVW * NC];
__device__ __align__(256) __nv_bfloat16 g_wal[(size_t)QKVW * NC];
__device__ __align__(256) __nv_bfloat16 g_wph[(size_t)NC * NC];
__device__ __align__(256) __nv_bfloat16 g_wpl[(size_t)NC * NC];
__device__ __align__(256) __nv_bfloat16 g_yh[(size_t)NB * NT * NC];
__device__ __align__(256) __nv_bfloat16 g_yl[(size_t)NB * NT * NC];
// split-bf16 qkv (written by gemm_mma epilogue, consumed by attn via cp.async)
__device__ __align__(256) __nv_bfloat16 g_kvh[(size_t)NB * NT * QKVW];
__device__ __align__(256) __nv_bfloat16 g_kvl[(size_t)NB * NT * QKVW];

// =========================== warp-MMA helpers (sm_80+ PTX) =================
__device__ __forceinline__ uint32_t smem_u32(const void* p) {
    uint32_t a;
    asm("{ .reg .u64 t; cvta.to.shared.u64 t, %1; cvt.u32.u64 %0, t; }" : "=r"(a) : "l"(p));
    return a;
}
__device__ __forceinline__ void mma16816(float* d, const uint32_t* a, const uint32_t* b) {
    asm volatile("mma.sync.aligned.m16n8k16.row.col.f32.bf16.bf16.f32 "
        "{%0,%1,%2,%3}, {%4,%5,%6,%7}, {%8,%9}, {%0,%1,%2,%3};"
        : "+f"(d[0]), "+f"(d[1]), "+f"(d[2]), "+f"(d[3])
        : "r"(a[0]), "r"(a[1]), "r"(a[2]), "r"(a[3]), "r"(b[0]), "r"(b[1]));
}
__device__ __forceinline__ void ldsm_x4(uint32_t* r, uint32_t addr) {
    asm volatile("ldmatrix.sync.aligned.m8n8.x4.shared.b16 {%0,%1,%2,%3}, [%4];"
        : "=r"(r[0]), "=r"(r[1]), "=r"(r[2]), "=r"(r[3]) : "r"(addr));
}
__device__ __forceinline__ void ldsm_x4t(uint32_t* r, uint32_t addr) {
    asm volatile("ldmatrix.sync.aligned.m8n8.x4.trans.shared.b16 {%0,%1,%2,%3}, [%4];"
        : "=r"(r[0]), "=r"(r[1]), "=r"(r[2]), "=r"(r[3]) : "r"(addr));
}
__device__ __forceinline__ void ldsm_x2(uint32_t* r, uint32_t addr) {
    asm volatile("ldmatrix.sync.aligned.m8n8.x2.shared.b16 {%0,%1}, [%2];"
        : "=r"(r[0]), "=r"(r[1]) : "r"(addr));
}
__device__ __forceinline__ void cp16(uint32_t dst, const void* src) {
    asm volatile("cp.async.cg.shared.global [%0], [%1], 16;" :: "r"(dst), "l"(src));
}
__device__ __forceinline__ uint32_t pack_bf16x2(float lo, float hi) {
    uint32_t r;
    asm("cvt.rn.bf16x2.f32 %0, %1, %2;" : "=r"(r) : "f"(hi), "f"(lo));
    return r;
}
__device__ __forceinline__ float bf16lo_f(uint32_t p) { return __uint_as_float(p << 16); }
__device__ __forceinline__ float bf16hi_f(uint32_t p) { return __uint_as_float(p & 0xffff0000u); }
__device__ __forceinline__ float ex2f(float x) {
    float r; asm("ex2.approx.f32 %0, %1;" : "=f"(r) : "f"(x)); return r;
}

// ---------------------------------------------------------------------------
// convert fp32 -> (hi bf16, lo bf16)
// ---------------------------------------------------------------------------
__global__ __launch_bounds__(256) void convert_hilo(
    const float* __restrict__ src, __nv_bfloat16* __restrict__ h,
    __nv_bfloat16* __restrict__ l, int n4)
{
    int i = blockIdx.x * 256 + threadIdx.x;
    if (i >= n4) return;
    float4 v = ((const float4*)src)[i];
    float vs[4] = {v.x, v.y, v.z, v.w};
    uint32_t hb[4], lb[4];
#pragma unroll
    for (int c = 0; c < 4; c++) {
        __nv_bfloat16 hh = __float2bfloat16(vs[c]);
        __nv_bfloat16 ll = __float2bfloat16(vs[c] - __bfloat162float(hh));
        hb[c] = __bfloat16_as_ushort(hh);
        lb[c] = __bfloat16_as_ushort(ll);
    }
    uint2 ho, lo;
    ho.x = hb[0] | (hb[1] << 16); ho.y = hb[2] | (hb[3] << 16);
    lo.x = lb[0] | (lb[1] << 16); lo.y = lb[2] | (lb[3] << 16);
    *(uint2*)(h + (size_t)i * 4) = ho;
    *(uint2*)(l + (size_t)i * 4) = lo;
}

// ---------------------------------------------------------------------------
// split-bf16 GEMM-NT + bias via mma.sync. Optional fused hi/lo bf16 output.
// CTA tile 128x128, 8 warps (64x32), BK=32, cp.async double buffered,
// 2 CTAs/SM (regs capped at 128).
// ---------------------------------------------------------------------------
#define APITCH 80
#define TILE_SB (128 * APITCH)
#define BUF_SB  (4 * TILE_SB)
#define GEMM_SMEM (2 * BUF_SB)

__global__ __launch_bounds__(256, 2) void gemm_mma(
    const __nv_bfloat16* __restrict__ Ah, const __nv_bfloat16* __restrict__ Al,
    const __nv_bfloat16* __restrict__ Bh, const __nv_bfloat16* __restrict__ Bl,
    const float* __restrict__ bias, float* __restrict__ C,
    __nv_bfloat16* __restrict__ Ch, __nv_bfloat16* __restrict__ Cl,
    int M, int N, int K)
{
    extern __shared__ char sm[];
    const uint32_t smem = smem_u32(sm);
    const int tid = threadIdx.x;
    const int wid = tid >> 5, lane = tid & 31;
    const int wr = wid >> 2, wc = wid & 3;
    const int bm = blockIdx.y * 128, bn = blockIdx.x * 128;

    const __nv_bfloat16* srcs[4] = {
        Ah + (size_t)bm * K, Al + (size_t)bm * K,
        Bh + (size_t)bn * K, Bl + (size_t)bn * K };

    float acc[4][4][4];
#pragma unroll
    for (int mt = 0; mt < 4; mt++)
#pragma unroll
        for (int nt = 0; nt < 4; nt++)
#pragma unroll
            for (int e = 0; e < 4; e++) acc[mt][nt][e] = 0.f;

    const int nch = K >> 5;

    auto issue = [&](int c) {
        const int k0 = c << 5;
        const uint32_t bofs = smem + (c & 1) * BUF_SB;
#pragma unroll
        for (int t = 0; t < 4; t++) {
            const __nv_bfloat16* sp = srcs[t];
#pragma unroll
            for (int i = 0; i < 2; i++) {
                int lin = tid + i * 256;
                int row = lin >> 2, g = lin & 3;
                cp16(bofs + (uint32_t)(t * TILE_SB + row * APITCH + g * 16),
                     sp + (size_t)row * K + k0 + g * 8);
            }
        }
        asm volatile("cp.async.commit_group;" ::: "memory");
    };

    issue(0);
    for (int c = 0; c < nch; ++c) {
        if (c + 1 < nch) {
            issue(c + 1);
            asm volatile("cp.async.wait_group 1;" ::: "memory");
        } else {
            asm volatile("cp.async.wait_group 0;" ::: "memory");
        }
        __syncthreads();

        const uint32_t bofs = smem + (c & 1) * BUF_SB;
        const uint32_t A_h = bofs;
        const uint32_t A_l = bofs + TILE_SB;
        const uint32_t B_h = bofs + 2 * TILE_SB;
        const uint32_t B_l = bofs + 3 * TILE_SB;
        const int ar = wr * 64 + (lane & 15);
        const int acg = (lane >> 4) & 1;
        const int br = wc * 32 + (lane & 7);
        const int bcg = (lane >> 3) & 1;

#pragma unroll
        for (int s = 0; s < 2; s++) {
            const uint32_t akoff = s * 32 + acg * 16;
            const uint32_t bkoff = s * 32 + bcg * 16;
            uint32_t ah[4][4], al[4][4], bh[4][2], bl[4][2];
#pragma unroll
            for (int mt = 0; mt < 4; mt++) {
                uint32_t rb = (uint32_t)((ar + mt * 16) * APITCH) + akoff;
                ldsm_x4(ah[mt], A_h + rb);
                ldsm_x4(al[mt], A_l + rb);
            }
#pragma unroll
            for (int nt = 0; nt < 4; nt++) {
                uint32_t rb = (uint32_t)((br + nt * 8) * APITCH) + bkoff;
                ldsm_x2(bh[nt], B_h + rb);
                ldsm_x2(bl[nt], B_l + rb);
            }
#pragma unroll
            for (int mt = 0; mt < 4; mt++)
#pragma unroll
                for (int nt = 0; nt < 4; nt++) {
                    mma16816(acc[mt][nt], ah[mt], bh[nt]);
                    mma16816(acc[mt][nt], ah[mt], bl[nt]);
                    mma16816(acc[mt][nt], al[mt], bh[nt]);
                }
        }
        __syncthreads();
    }

    const int r0 = lane >> 2, c0 = (lane & 3) * 2;
#pragma unroll
    for (int mt = 0; mt < 4; mt++) {
#pragma unroll
        for (int nt = 0; nt < 4; nt++) {
            int col = bn + wc * 32 + nt * 8 + c0;
            float b0 = bias[col], b1 = bias[col + 1];
            int row = bm + wr * 64 + mt * 16 + r0;
            float v0 = acc[mt][nt][0] + b0, v1 = acc[mt][nt][1] + b1;
            float v2 = acc[mt][nt][2] + b0, v3 = acc[mt][nt][3] + b1;
            *(float2*)&C[(size_t)row * N + col] = make_float2(v0, v1);
            *(float2*)&C[(size_t)(row + 8) * N + col] = make_float2(v2, v3);
            if (Ch) {
                uint32_t h0 = pack_bf16x2(v0, v1);
                uint32_t h1 = pack_bf16x2(v2, v3);
                uint32_t l0 = pack_bf16x2(v0 - bf16lo_f(h0), v1 - bf16hi_f(h0));
                uint32_t l1 = pack_bf16x2(v2 - bf16lo_f(h1), v3 - bf16hi_f(h1));
                *(uint32_t*)&Ch[(size_t)row * N + col] = h0;
                *(uint32_t*)&Ch[(size_t)(row + 8) * N + col] = h1;
                *(uint32_t*)&Cl[(size_t)row * N + col] = l0;
                *(uint32_t*)&Cl[(size_t)(row + 8) * N + col] = l1;
            }
        }
    }
}

// ---------------------------------------------------------------------------
// Head-0 selection scores: S[b,i,j] = (1<=j<i) ? max(0, 0.125*q0[i].k0[j]) : 0
// ---------------------------------------------------------------------------
__global__ __launch_bounds__(256) void score0_kernel()
{
    const int jt = blockIdx.x, it = blockIdx.y, b = blockIdx.z;
    const int tid = threadIdx.x;
    const int ty = tid >> 4, tx = tid & 15;

    if (jt > it) {
        float4 z = make_float4(0.f, 0.f, 0.f, 0.f);
#pragma unroll
        for (int l = 0; l < 4; l++) {
            int lin = tid + l * 256;
            int r = lin >> 4, cg = (lin & 15) << 2;
            *(float4*)&g_S[((size_t)(b * NT) + it * 64 + r) * NT + jt * 64 + cg] = z;
        }
        return;
    }

    __shared__ float qts[64 * 68];
    __shared__ float kts[64 * 68];
    const float* qb = g_qkv + ((size_t)(b * NT) + it * 64) * QKVW;
    const float* kb = g_qkv + ((size_t)(b * NT) + jt * 64) * QKVW + 768;
#pragma unroll
    for (int l = 0; l < 4; l++) {
        int lin = tid + l * 256;
        int r = lin >> 4, dg = (lin & 15) << 2;
        float4 qv = *(const float4*)&qb[(size_t)r * QKVW + dg];
        qts[(dg + 0) * 68 + r] = qv.x; qts[(dg + 1) * 68 + r] = qv.y;
        qts[(dg + 2) * 68 + r] = qv.z; qts[(dg + 3) * 68 + r] = qv.w;
        float4 kv = *(const float4*)&kb[(size_t)r * QKVW + dg];
        kts[(dg + 0) * 68 + r] = kv.x; kts[(dg + 1) * 68 + r] = kv.y;
        kts[(dg + 2) * 68 + r] = kv.z; kts[(dg + 3) * 68 + r] = kv.w;
    }
    __syncthreads();

    float s[4][4];
#pragma unroll
    for (int r = 0; r < 4; r++)
#pragma unroll
        for (int c = 0; c < 4; c++) s[r][c] = 0.f;

#pragma unroll 16
    for (int d = 0; d < 64; d++) {
        float4 qa = *(const float4*)&qts[d * 68 + ty * 4];
        float4 ka = *(const float4*)&kts[d * 68 + tx * 4];
        float qr[4] = {qa.x, qa.y, qa.z, qa.w};
        float kr[4] = {ka.x, ka.y, ka.z, ka.w};
#pragma unroll
        for (int r = 0; r < 4; r++)
#pragma unroll
            for (int c = 0; c < 4; c++) s[r][c] += qr[r] * kr[c];
    }

#pragma unroll
    for (int r = 0; r < 4; r++) {
        int i = it * 64 + ty * 4 + r;
        float o[4];
#pragma unroll
        for (int c = 0; c < 4; c++) {
            int j = jt * 64 + tx * 4 + c;
            float v = s[r][c] * 0.125f;
            o[c] = (j >= 1 && j < i) ? fmaxf(v, 0.f) : 0.f;
        }
        *(float4*)&g_S[((size_t)(b * NT) + i) * NT + jt * 64 + tx * 4] =
            make_float4(o[0], o[1], o[2], o[3]);
    }
}

// ---------------------------------------------------------------------------
// Column scan:  F[b,i,j] = sum_{i'<i} S[b,i',j]
// ---------------------------------------------------------------------------
__global__ __launch_bounds__(256) void colsum_kernel()
{
    int j = blockIdx.x * 256 + threadIdx.x;
    int b = blockIdx.y >> 6, ch = blockIdx.y & 63;
    const float* p = g_S + ((size_t)(b * NT) + ch * CHROWS) * NT + j;
    float s = 0.f;
    for (int r = 0; r < CHROWS; r++) s += p[(size_t)r * NT];
    g_csum[(b * NCHUNK + ch) * NT + j] = s;
}

__global__ __launch_bounds__(256) void scan_kernel()
{
    int j = blockIdx.x * 256 + threadIdx.x;
    int b = blockIdx.y >> 6, ch = blockIdx.y & 63;
    float run = 0.f;
    for (int c = 0; c < ch; c++) run += g_csum[(b * NCHUNK + c) * NT + j];
    size_t base = ((size_t)(b * NT) + ch * CHROWS) * NT + j;
    for (int r = 0; r < CHROWS; r++) {
        size_t idx = base + (size_t)r * NT;
        float sv = g_S[idx];
        g_F[idx] = run;
        run += sv;
    }
}

// ---------------------------------------------------------------------------
// MMA flash attention with cp.async double-buffered split-bf16 K/V.
// SMEM rows are 128B (64 bf16), 16B-chunk XOR swizzle: conflict-free for
// cp.async stores and ldmatrix (normal + trans) reads.
// ---------------------------------------------------------------------------
#define QT_B 16384                   // 128 rows x 128 B
#define KVT_B 8192                   // 64 rows x 128 B
#define KVBUF_B (4 * KVT_B)          // kh, kl, vh, vl
#define ATT_SMEM (2 * QT_B + 2 * KVBUF_B)   // 98304

__global__ __launch_bounds__(256, 1) void attn_mma()
{
    extern __shared__ char smc[];
    const uint32_t s_qh = smem_u32(smc);
    const uint32_t s_ql = s_qh + QT_B;
    const uint32_t s_kv0 = s_ql + QT_B;

    const int qi = gridDim.x - 1 - blockIdx.x;     // heavy tiles first
    const int h = blockIdx.y, b = blockIdx.z;
    const int tid = threadIdx.x;
    const int w = tid >> 5, lane = tid & 31;
    const int g = lane >> 2, t4 = lane & 3;
    const int i0 = qi * 128;

    const float SCL = 0.125f * 1.44269504f;
    const float FL2 = 1.44269504f;

    // ---- issue Q (hi/lo) via cp.async ----
    {
        const size_t qbase = ((size_t)(b * NT) + i0) * QKVW + h * 64;
#pragma unroll
        for (int u = 0; u < 8; u++) {
            int half = u >> 2;
            int rem = ((u & 3) << 8) + tid;
            int row = rem >> 3, cg = rem & 7;
            const __nv_bfloat16* src =
                (half ? g_kvl : g_kvh) + qbase + (size_t)row * QKVW + cg * 8;
            uint32_t dst = (half ? s_ql : s_qh) + row * 128 + ((cg ^ (row & 7)) << 4);
            cp16(dst, src);
        }
    }

    auto issue_kv = [&](int kt, uint32_t kvb) {
        const size_t rb = ((size_t)(b * NT) + kt * 64) * QKVW + h * 64;
#pragma unroll
        for (int u = 0; u < 8; u++) {
            int t = u >> 1;                        // 0=kh 1=kl 2=vh 3=vl
            int rem = ((u & 1) << 8) + tid;
            int row = rem >> 3, cg = rem & 7;
            size_t off = rb + (size_t)row * QKVW + ((t >> 1) ? 1536 : 768) + cg * 8;
            const __nv_bfloat16* src = ((t & 1) ? g_kvl : g_kvh) + off;
            uint32_t dst = kvb + t * KVT_B + row * 128 + ((cg ^ (row & 7)) << 4);
            cp16(dst, src);
        }
    };

    issue_kv(0, s_kv0);
    asm volatile("cp.async.commit_group;" ::: "memory");

    uint32_t qfh[4][4], qfl[4][4];

    float yacc[8][4];
#pragma unroll
    for (int nt = 0; nt < 8; nt++)
#pragma unroll
        for (int e = 0; e < 4; e++) yacc[nt][e] = 0.f;
    float m0 = -INFINITY, m1 = -INFINITY, ls0 = 0.f, ls1 = 0.f;

    const int i_r0 = i0 + w * 16 + g;
    const int i_r1 = i_r0 + 8;
    const int ktend = 2 * qi + 2;
    const int rl = lane & 7, s8 = (lane >> 3) & 1, s16 = lane >> 4;

    for (int kt = 0; kt < ktend; kt++) {
        if (kt + 1 < ktend) {
            issue_kv(kt + 1, s_kv0 + ((kt + 1) & 1) * KVBUF_B);
            asm volatile("cp.async.commit_group;" ::: "memory");
            asm volatile("cp.async.wait_group 1;" ::: "memory");
        } else {
            asm volatile("cp.async.wait_group 0;" ::: "memory");
        }
        __syncthreads();

        if (kt == 0) {
            // Q A-fragments (persistent)
            int qrow = w * 16 + (lane & 15);
            int qs = (lane >> 4) & 1;
#pragma unroll
            for (int s = 0; s < 4; s++) {
                int cg = 2 * s + qs;
                uint32_t a = (uint32_t)(qrow * 128) + ((cg ^ (qrow & 7)) << 4);
                ldsm_x4(qfh[s], s_qh + a);
                ldsm_x4(qfl[s], s_ql + a);
            }
        }

        const uint32_t kh = s_kv0 + (kt & 1) * KVBUF_B;
        const uint32_t kl = kh + KVT_B;
        const uint32_t vh = kh + 2 * KVT_B;
        const uint32_t vl = kh + 3 * KVT_B;

        // ---- S = Q K^T (3-pass split) ----
        float sa[8][4];
#pragma unroll
        for (int nt = 0; nt < 8; nt++)
#pragma unroll
            for (int e = 0; e < 4; e++) sa[nt][e] = 0.f;

#pragma unroll
        for (int s = 0; s < 4; s++) {
            const int cgk = 2 * s + s8;
            const uint32_t koff = (uint32_t)((cgk ^ rl) << 4);
#pragma unroll
            for (int p = 0; p < 4; p++) {
                uint32_t addr = (uint32_t)((((2 * p + s16) * 8 + rl) * 128)) + koff;
                uint32_t bh[4], bl[4];
                ldsm_x4(bh, kh + addr);
                ldsm_x4(bl, kl + addr);
                mma16816(sa[2 * p],     qfh[s], &bh[0]);
                mma16816(sa[2 * p],     qfh[s], &bl[0]);
                mma16816(sa[2 * p],     qfl[s], &bh[0]);
                mma16816(sa[2 * p + 1], qfh[s], &bh[2]);
                mma16816(sa[2 * p + 1], qfh[s], &bl[2]);
                mma16816(sa[2 * p + 1], qfl[s], &bh[2]);
            }
        }

        // ---- softmax (base-2), logits = sa*SCL - F*FL2 ----
        const float* F0 = g_F + ((size_t)(b * NT) + i_r0) * NT + kt * 64 + 2 * t4;
        const float* F1 = F0 + (size_t)8 * NT;
        const bool edge = (kt >= 2 * qi);
        const int jb = kt * 64 + 2 * t4;
        float mt0 = -INFINITY, mt1 = -INFINITY;
#pragma unroll
        for (int nt = 0; nt < 8; nt++) {
            float2 f0 = *(const float2*)(F0 + nt * 8);
            float2 f1 = *(const float2*)(F1 + nt * 8);
            float v0 = sa[nt][0] * SCL - f0.x * FL2;
            float v1 = sa[nt][1] * SCL - f0.y * FL2;
            float v2 = sa[nt][2] * SCL - f1.x * FL2;
            float v3 = sa[nt][3] * SCL - f1.y * FL2;
            if (edge) {
                int j0 = jb + nt * 8;
                if (j0 > i_r0) v0 = -INFINITY;
                if (j0 + 1 > i_r0) v1 = -INFINITY;
                if (j0 > i_r1) v2 = -INFINITY;
                if (j0 + 1 > i_r1) v3 = -INFINITY;
            }
            sa[nt][0] = v0; sa[nt][1] = v1; sa[nt][2] = v2; sa[nt][3] = v3;
            mt0 = fmaxf(mt0, fmaxf(v0, v1));
            mt1 = fmaxf(mt1, fmaxf(v2, v3));
        }
        mt0 = fmaxf(mt0, __shfl_xor_sync(0xffffffffu, mt0, 1));
        mt0 = fmaxf(mt0, __shfl_xor_sync(0xffffffffu, mt0, 2));
        mt1 = fmaxf(mt1, __shfl_xor_sync(0xffffffffu, mt1, 1));
        mt1 = fmaxf(mt1, __shfl_xor_sync(0xffffffffu, mt1, 2));
        float mn0 = fmaxf(m0, mt0), mn1 = fmaxf(m1, mt1);
        float sc0 = ex2f(m0 - mn0), sc1 = ex2f(m1 - mn1);
        m0 = mn0; m1 = mn1;

        uint32_t pfh01[8], pfh23[8], pfl01[8], pfl23[8];
        float rs0 = 0.f, rs1 = 0.f;
#pragma unroll
        for (int nt = 0; nt < 8; nt++) {
            float p0 = ex2f(sa[nt][0] - m0);
            float p1 = ex2f(sa[nt][1] - m0);
            float p2 = ex2f(sa[nt][2] - m1);
            float p3 = ex2f(sa[nt][3] - m1);
            rs0 += p0 + p1; rs1 += p2 + p3;
            uint32_t h01 = pack_bf16x2(p0, p1);
            uint32_t h23 = pack_bf16x2(p2, p3);
            pfh01[nt] = h01; pfh23[nt] = h23;
            pfl01[nt] = pack_bf16x2(p0 - bf16lo_f(h01), p1 - bf16hi_f(h01));
            pfl23[nt] = pack_bf16x2(p2 - bf16lo_f(h23), p3 - bf16hi_f(h23));
        }
        ls0 = ls0 * sc0 + rs0;
        ls1 = ls1 * sc1 + rs1;
#pragma unroll
        for (int nt = 0; nt < 8; nt++) {
            yacc[nt][0] *= sc0; yacc[nt][1] *= sc0;
            yacc[nt][2] *= sc1; yacc[nt][3] *= sc1;
        }

        // ---- y += P V (3-pass split), V via ldsm trans ----
#pragma unroll
        for (int s = 0; s < 4; s++) {
            uint32_t ah[4] = { pfh01[2 * s], pfh23[2 * s], pfh01[2 * s + 1], pfh23[2 * s + 1] };
            uint32_t al[4] = { pfl01[2 * s], pfl23[2 * s], pfl01[2 * s + 1], pfl23[2 * s + 1] };
            const uint32_t vrow = (uint32_t)((16 * s + s8 * 8 + rl) * 128);
#pragma unroll
            for (int p = 0; p < 4; p++) {
                uint32_t addr = vrow + (uint32_t)((((2 * p + s16)) ^ rl) << 4);
                uint32_t vhf[4], vlf[4];
                ldsm_x4t(vhf, vh + addr);
                ldsm_x4t(vlf, vl + addr);
                mma16816(yacc[2 * p],     ah, &vhf[0]);
                mma16816(yacc[2 * p],     ah, &vlf[0]);
                mma16816(yacc[2 * p],     al, &vhf[0]);
                mma16816(yacc[2 * p + 1], ah, &vhf[2]);
                mma16816(yacc[2 * p + 1], ah, &vlf[2]);
                mma16816(yacc[2 * p + 1], al, &vhf[2]);
            }
        }
        __syncthreads();    // all reads of this buffer done before next overwrite
    }

    // ---- finalize ----
    ls0 += __shfl_xor_sync(0xffffffffu, ls0, 1);
    ls0 += __shfl_xor_sync(0xffffffffu, ls0, 2);
    ls1 += __shfl_xor_sync(0xffffffffu, ls1, 1);
    ls1 += __shfl_xor_sync(0xffffffffu, ls1, 2);
    float inv0 = 1.0f / ls0, inv1 = 1.0f / ls1;
    float* y0 = g_y + ((size_t)(b * NT) + i_r0) * (NH * ND) + h * 64 + 2 * t4;
    float* y1 = g_y + ((size_t)(b * NT) + i_r1) * (NH * ND) + h * 64 + 2 * t4;
#pragma unroll
    for (int nt = 0; nt < 8; nt++) {
        *(float2*)(y0 + nt * 8) = make_float2(yacc[nt][0] * inv0, yacc[nt][1] * inv0);
        *(float2*)(y1 + nt * 8) = make_float2(yacc[nt][2] * inv1, yacc[nt][3] * inv1);
    }
}

// ---------------------------------------------------------------------------
extern "C" void kernel_launch(void* const* d_in, const int* in_sizes, int n_in,
                              void* d_out, int out_size)
{
    (void)in_sizes; (void)n_in; (void)out_size;
    const float* x      = (const float*)d_in[0];
    const float* w_attn = (const float*)d_in[1];
    const float* b_attn = (const float*)d_in[2];
    const float* w_proj = (const float*)d_in[3];
    const float* b_proj = (const float*)d_in[4];
    float* out = (float*)d_out;

    float *qkv = nullptr, *y = nullptr;
    cudaGetSymbolAddress((void**)&qkv, g_qkv);
    cudaGetSymbolAddress((void**)&y, g_y);
    __nv_bfloat16 *xh, *xl, *wah, *wal, *wph, *wpl, *yh, *yl, *kvh, *kvl;
    cudaGetSymbolAddress((void**)&xh, g_xh);   cudaGetSymbolAddress((void**)&xl, g_xl);
    cudaGetSymbolAddress((void**)&wah, g_wah); cudaGetSymbolAddress((void**)&wal, g_wal);
    cudaGetSymbolAddress((void**)&wph, g_wph); cudaGetSymbolAddress((void**)&wpl, g_wpl);
    cudaGetSymbolAddress((void**)&yh, g_yh);   cudaGetSymbolAddress((void**)&yl, g_yl);
    cudaGetSymbolAddress((void**)&kvh, g_kvh); cudaGetSymbolAddress((void**)&kvl, g_kvl);

    cudaFuncSetAttribute(gemm_mma,
                         cudaFuncAttributeMaxDynamicSharedMemorySize, GEMM_SMEM);
    cudaFuncSetAttribute(attn_mma,
                         cudaFuncAttributeMaxDynamicSharedMemorySize, ATT_SMEM);

    // 0) split-bf16 conversions of x, w_attn, w_proj
    {
        int n4x = (NB * NT * NC) / 4;
        convert_hilo<<<(n4x + 255) / 256, 256>>>(x, xh, xl, n4x);
        int n4a = (QKVW * NC) / 4;
        convert_hilo<<<(n4a + 255) / 256, 256>>>(w_attn, wah, wal, n4a);
        int n4p = (NC * NC) / 4;
        convert_hilo<<<(n4p + 255) / 256, 256>>>(w_proj, wph, wpl, n4p);
    }

    // 1) QKV projection (+ fused hi/lo bf16 output for attention)
    gemm_mma<<<dim3(QKVW / 128, (NB * NT) / 128), 256, GEMM_SMEM>>>(
        xh, xl, wah, wal, b_attn, qkv, kvh, kvl, NB * NT, QKVW, NC);

    // 2) head-0 masked relu scores -> g_S
    score0_kernel<<<dim3(NT / 64, NT / 64, NB), 256>>>();

    // 3) exclusive column cumsum -> g_F
    colsum_kernel<<<dim3(NT / 256, NB * NCHUNK), 256>>>();
    scan_kernel<<<dim3(NT / 256, NB * NCHUNK), 256>>>();

    // 4) MMA flash attention (cp.async pipelined) -> g_y
    attn_mma<<<dim3(NT / 128, NH, NB), 256, ATT_SMEM>>>();

    // 5) convert y, output projection: [4096,768] x [768,768]^T -> out
    {
        int n4y = (NB * NT * NC) / 4;
        convert_hilo<<<(n4y + 255) / 256, 256>>>(y, yh, yl, n4y);
    }
    gemm_mma<<<dim3(NC / 128, (NB * NT) / 128), 256, GEMM_SMEM>>>(
        yh, yl, wph, wpl, b_proj, out, nullptr, nullptr, NB * NT, NC, NC);
}

// round 15
// speedup vs baseline: 2.7188x; 1.0781x over previous
#include <cuda_runtime.h>
#include <cuda_bf16.h>
#include <math.h>
#include <stdint.h>

#define NB 2
#define NT 2048
#define NC 768
#define NH 12
#define ND 64
#define QKVW 2304
#define NCHUNK 64
#define CHROWS 32

// ---------------- scratch (device globals; no allocation allowed) ----------
__device__ __align__(256) float g_qkv[(size_t)NB * NT * QKVW];
__device__ __align__(256) float g_S[(size_t)NB * NT * NT];
__device__ __align__(256) float g_F[(size_t)NB * NT * NT];
__device__ __align__(256) float g_csum[NB * NCHUNK * NT];
__device__ __align__(256) float g_y[(size_t)NB * NT * (NH * ND)];
// split-bf16 copies
__device__ __align__(256) __nv_bfloat16 g_xh[(size_t)NB * NT * NC];
__device__ __align__(256) __nv_bfloat16 g_xl[(size_t)NB * NT * NC];
__device__ __align__(256) __nv_bfloat16 g_wah[(size_t)QKVW * NC];
__device__ __align__(256) __nv_bfloat16 g_wal[(size_t)QKVW * NC];
__device__ __align__(256) __nv_bfloat16 g_wph[(size_t)NC * NC];
__device__ __align__(256) __nv_bfloat16 g_wpl[(size_t)NC * NC];
__device__ __align__(256) __nv_bfloat16 g_yh[(size_t)NB * NT * NC];
__device__ __align__(256) __nv_bfloat16 g_yl[(size_t)NB * NT * NC];
// split-bf16 qkv (written by gemm_mma epilogue)
__device__ __align__(256) __nv_bfloat16 g_kvh[(size_t)NB * NT * QKVW];
__device__ __align__(256) __nv_bfloat16 g_kvl[(size_t)NB * NT * QKVW];

// =========================== warp-MMA helpers (sm_80+ PTX) =================
__device__ __forceinline__ uint32_t smem_u32(const void* p) {
    uint32_t a;
    asm("{ .reg .u64 t; cvta.to.shared.u64 t, %1; cvt.u32.u64 %0, t; }" : "=r"(a) : "l"(p));
    return a;
}
__device__ __forceinline__ void mma16816(float* d, const uint32_t* a, const uint32_t* b) {
    asm volatile("mma.sync.aligned.m16n8k16.row.col.f32.bf16.bf16.f32 "
        "{%0,%1,%2,%3}, {%4,%5,%6,%7}, {%8,%9}, {%0,%1,%2,%3};"
        : "+f"(d[0]), "+f"(d[1]), "+f"(d[2]), "+f"(d[3])
        : "r"(a[0]), "r"(a[1]), "r"(a[2]), "r"(a[3]), "r"(b[0]), "r"(b[1]));
}
__device__ __forceinline__ void ldsm_x4(uint32_t* r, uint32_t addr) {
    asm volatile("ldmatrix.sync.aligned.m8n8.x4.shared.b16 {%0,%1,%2,%3}, [%4];"
        : "=r"(r[0]), "=r"(r[1]), "=r"(r[2]), "=r"(r[3]) : "r"(addr));
}
__device__ __forceinline__ void ldsm_x4t(uint32_t* r, uint32_t addr) {
    asm volatile("ldmatrix.sync.aligned.m8n8.x4.trans.shared.b16 {%0,%1,%2,%3}, [%4];"
        : "=r"(r[0]), "=r"(r[1]), "=r"(r[2]), "=r"(r[3]) : "r"(addr));
}
__device__ __forceinline__ void cp16(uint32_t dst, const void* src) {
    asm volatile("cp.async.cg.shared.global [%0], [%1], 16;" :: "r"(dst), "l"(src));
}
__device__ __forceinline__ uint32_t pack_bf16x2(float lo, float hi) {
    uint32_t r;
    asm("cvt.rn.bf16x2.f32 %0, %1, %2;" : "=r"(r) : "f"(hi), "f"(lo));
    return r;
}
__device__ __forceinline__ float bf16lo_f(uint32_t p) { return __uint_as_float(p << 16); }
__device__ __forceinline__ float bf16hi_f(uint32_t p) { return __uint_as_float(p & 0xffff0000u); }
__device__ __forceinline__ float ex2f(float x) {
    float r; asm("ex2.approx.f32 %0, %1;" : "=f"(r) : "f"(x)); return r;
}

// ---------------------------------------------------------------------------
// convert fp32 -> (hi bf16, lo bf16)
// ---------------------------------------------------------------------------
__global__ __launch_bounds__(256) void convert_hilo(
    const float* __restrict__ src, __nv_bfloat16* __restrict__ h,
    __nv_bfloat16* __restrict__ l, int n4)
{
    int i = blockIdx.x * 256 + threadIdx.x;
    if (i >= n4) return;
    float4 v = ((const float4*)src)[i];
    float vs[4] = {v.x, v.y, v.z, v.w};
    uint32_t hb[4], lb[4];
#pragma unroll
    for (int c = 0; c < 4; c++) {
        __nv_bfloat16 hh = __float2bfloat16(vs[c]);
        __nv_bfloat16 ll = __float2bfloat16(vs[c] - __bfloat162float(hh));
        hb[c] = __bfloat16_as_ushort(hh);
        lb[c] = __bfloat16_as_ushort(ll);
    }
    uint2 ho, lo;
    ho.x = hb[0] | (hb[1] << 16); ho.y = hb[2] | (hb[3] << 16);
    lo.x = lb[0] | (lb[1] << 16); lo.y = lb[2] | (lb[3] << 16);
    *(uint2*)(h + (size_t)i * 4) = ho;
    *(uint2*)(l + (size_t)i * 4) = lo;
}

// ---------------------------------------------------------------------------
// split-bf16 GEMM-NT + bias via mma.sync, 3-stage cp.async, 1 barrier/chunk.
// Combined hi/lo tiles: 128 rows x 128B, logical 16B chunk lcg (0-3 = hi k,
// 4-7 = lo k), phys chunk = lcg ^ (row&7). 2 CTAs/SM.
// ---------------------------------------------------------------------------
#define CTILE 16384                    // 128 rows x 128 B (hi+lo combined)
#define STAGE_B (2 * CTILE)            // A + B
#define GEMM_SMEM (3 * STAGE_B)        // 98304

__global__ __launch_bounds__(256, 2) void gemm_mma(
    const __nv_bfloat16* __restrict__ Ah, const __nv_bfloat16* __restrict__ Al,
    const __nv_bfloat16* __restrict__ Bh, const __nv_bfloat16* __restrict__ Bl,
    const float* __restrict__ bias, float* __restrict__ C,
    __nv_bfloat16* __restrict__ Ch, __nv_bfloat16* __restrict__ Cl,
    int M, int N, int K)
{
    extern __shared__ char sm[];
    const uint32_t smem = smem_u32(sm);
    const int tid = threadIdx.x;
    const int wid = tid >> 5, lane = tid & 31;
    const int wr = wid >> 2, wc = wid & 3;
    const int bm = blockIdx.y * 128, bn = blockIdx.x * 128;

    const __nv_bfloat16* srcs[4] = {
        Ah + (size_t)bm * K, Al + (size_t)bm * K,
        Bh + (size_t)bn * K, Bl + (size_t)bn * K };

    float acc[4][4][4];
#pragma unroll
    for (int mt = 0; mt < 4; mt++)
#pragma unroll
        for (int nt = 0; nt < 4; nt++)
#pragma unroll
            for (int e = 0; e < 4; e++) acc[mt][nt][e] = 0.f;

    const int nch = K >> 5;

    auto issue = [&](int c) {
        const int k0 = c << 5;
        const uint32_t bofs = smem + (c % 3) * STAGE_B;
#pragma unroll
        for (int t = 0; t < 2; t++) {
#pragma unroll
            for (int i = 0; i < 4; i++) {
                int rem = i * 256 + tid;
                int row = rem >> 3, lcg = rem & 7;
                const __nv_bfloat16* sp = srcs[t * 2 + (lcg >> 2)];
                cp16(bofs + (uint32_t)(t * CTILE + row * 128 + (((lcg ^ row) & 7) << 4)
                             + (lcg & ~7u ? 0 : 0)) + (uint32_t)((lcg & 4) ? ((4 ^ 0) & 0) : 0)
                     , sp);  // placeholder (overwritten below)
            }
        }
    };
    // NOTE: lambda above replaced by explicit function-style code below.
    (void)issue;

    auto issue2 = [&](int c) {
        const int k0 = c << 5;
        const uint32_t bofs = smem + (c % 3) * STAGE_B;
#pragma unroll
        for (int t = 0; t < 2; t++) {
#pragma unroll
            for (int i = 0; i < 4; i++) {
                int rem = i * 256 + tid;
                int row = rem >> 3, lcg = rem & 7;
                const __nv_bfloat16* sp = srcs[t * 2 + (lcg >> 2)];
                uint32_t dst = bofs + (uint32_t)(t * CTILE + row * 128
                                + ((lcg ^ (row & 7)) << 4));
                cp16(dst, sp + (size_t)row * K + k0 + (lcg & 3) * 8);
            }
        }
        asm volatile("cp.async.commit_group;" ::: "memory");
    };

    issue2(0);
    issue2(1);

    const int ar = wr * 64 + (lane & 15);
    const int acg = (lane >> 4) & 1;
    const int rl = lane & 7, s8 = (lane >> 3) & 1, s16 = lane >> 4;

    for (int c = 0; c < nch; ++c) {
        if (c + 1 < nch) {
            asm volatile("cp.async.wait_group 1;" ::: "memory");
        } else {
            asm volatile("cp.async.wait_group 0;" ::: "memory");
        }
        __syncthreads();
        if (c + 2 < nch) issue2(c + 2);

        const uint32_t bofs = smem + (c % 3) * STAGE_B;
        const uint32_t A_ = bofs;
        const uint32_t B_ = bofs + CTILE;

#pragma unroll
        for (int s = 0; s < 2; s++) {
            const int cga_h = 2 * s + acg, cga_l = cga_h + 4;
            const int cgb_h = 2 * s + s8, cgb_l = cgb_h + 4;
            uint32_t ah[4][4], al[4][4], bh[2][4], bl[2][4];
#pragma unroll
            for (int mt = 0; mt < 4; mt++) {
                int row = ar + mt * 16;
                ldsm_x4(ah[mt], A_ + (uint32_t)(row * 128 + ((cga_h ^ rl) << 4)));
                ldsm_x4(al[mt], A_ + (uint32_t)(row * 128 + ((cga_l ^ rl) << 4)));
            }
#pragma unroll
            for (int pp = 0; pp < 2; pp++) {
                int rowB = wc * 32 + pp * 16 + s16 * 8 + rl;
                ldsm_x4(bh[pp], B_ + (uint32_t)(rowB * 128 + ((cgb_h ^ rl) << 4)));
                ldsm_x4(bl[pp], B_ + (uint32_t)(rowB * 128 + ((cgb_l ^ rl) << 4)));
            }
#pragma unroll
            for (int mt = 0; mt < 4; mt++)
#pragma unroll
                for (int nt = 0; nt < 4; nt++) {
                    const uint32_t* bhp = &bh[nt >> 1][(nt & 1) * 2];
                    const uint32_t* blp = &bl[nt >> 1][(nt & 1) * 2];
                    mma16816(acc[mt][nt], ah[mt], bhp);
                    mma16816(acc[mt][nt], ah[mt], blp);
                    mma16816(acc[mt][nt], al[mt], bhp);
                }
        }
    }

    const int r0 = lane >> 2, c0 = (lane & 3) * 2;
#pragma unroll
    for (int mt = 0; mt < 4; mt++) {
#pragma unroll
        for (int nt = 0; nt < 4; nt++) {
            int col = bn + wc * 32 + nt * 8 + c0;
            float b0 = bias[col], b1 = bias[col + 1];
            int row = bm + wr * 64 + mt * 16 + r0;
            float v0 = acc[mt][nt][0] + b0, v1 = acc[mt][nt][1] + b1;
            float v2 = acc[mt][nt][2] + b0, v3 = acc[mt][nt][3] + b1;
            *(float2*)&C[(size_t)row * N + col] = make_float2(v0, v1);
            *(float2*)&C[(size_t)(row + 8) * N + col] = make_float2(v2, v3);
            if (Ch) {
                uint32_t h0 = pack_bf16x2(v0, v1);
                uint32_t h1 = pack_bf16x2(v2, v3);
                uint32_t l0 = pack_bf16x2(v0 - bf16lo_f(h0), v1 - bf16hi_f(h0));
                uint32_t l1 = pack_bf16x2(v2 - bf16lo_f(h1), v3 - bf16hi_f(h1));
                *(uint32_t*)&Ch[(size_t)row * N + col] = h0;
                *(uint32_t*)&Ch[(size_t)(row + 8) * N + col] = h1;
                *(uint32_t*)&Cl[(size_t)row * N + col] = l0;
                *(uint32_t*)&Cl[(size_t)(row + 8) * N + col] = l1;
            }
        }
    }
}

// ---------------------------------------------------------------------------
// Head-0 selection scores via mma.sync (split-bf16 3-pass):
// S[b,i,j] = (1<=j<i) ? max(0, 0.125*q0[i].k0[j]) : 0   64x64 tile / block.
// ---------------------------------------------------------------------------
__global__ __launch_bounds__(128) void score0_mma()
{
    const int jt = blockIdx.x, it = blockIdx.y, b = blockIdx.z;
    const int tid = threadIdx.x;

    if (jt > it) {
        float4 z = make_float4(0.f, 0.f, 0.f, 0.f);
#pragma unroll
        for (int u = 0; u < 8; u++) {
            int lin = u * 128 + tid;
            int row = lin >> 4, cg = (lin & 15) << 2;
            *(float4*)&g_S[((size_t)(b * NT) + it * 64 + row) * NT + jt * 64 + cg] = z;
        }
        return;
    }

    __shared__ __align__(128) char smc[32768];
    const uint32_t s_qh = smem_u32(smc);
    const uint32_t s_ql = s_qh + 8192;
    const uint32_t s_kh = s_qh + 16384;
    const uint32_t s_kl = s_qh + 24576;
    const int w = tid >> 5, lane = tid & 31;

    const size_t qb = ((size_t)(b * NT) + it * 64) * QKVW;
    const size_t kb = ((size_t)(b * NT) + jt * 64) * QKVW + 768;
#pragma unroll
    for (int u = 0; u < 4; u++) {
        int rem = u * 128 + tid;
        int row = rem >> 3, cg = rem & 7;
        uint32_t off = (uint32_t)(row * 128 + ((cg ^ (row & 7)) << 4));
        size_t so = (size_t)row * QKVW + cg * 8;
        cp16(s_qh + off, g_kvh + qb + so);
        cp16(s_ql + off, g_kvl + qb + so);
        cp16(s_kh + off, g_kvh + kb + so);
        cp16(s_kl + off, g_kvl + kb + so);
    }
    asm volatile("cp.async.commit_group;" ::: "memory");
    asm volatile("cp.async.wait_group 0;" ::: "memory");
    __syncthreads();

    float sa[8][4];
#pragma unroll
    for (int nt = 0; nt < 8; nt++)
#pragma unroll
        for (int e = 0; e < 4; e++) sa[nt][e] = 0.f;

    const int qrow = w * 16 + (lane & 15);
    const int acg = (lane >> 4) & 1;
    const int rl = lane & 7, s8 = (lane >> 3) & 1, s16 = lane >> 4;

#pragma unroll
    for (int s = 0; s < 4; s++) {
        uint32_t ah[4], al[4];
        {
            int cgh = 2 * s + acg;
            uint32_t a = (uint32_t)(qrow * 128 + ((cgh ^ (qrow & 7)) << 4));
            ldsm_x4(ah, s_qh + a);
            ldsm_x4(al, s_ql + a);
        }
        const int cgb = 2 * s + s8;
#pragma unroll
        for (int pp = 0; pp < 4; pp++) {
            int rowB = pp * 16 + s16 * 8 + rl;
            uint32_t addr = (uint32_t)(rowB * 128 + ((cgb ^ rl) << 4));
            uint32_t bh[4], bl[4];
            ldsm_x4(bh, s_kh + addr);
            ldsm_x4(bl, s_kl + addr);
            mma16816(sa[2 * pp],     ah, &bh[0]);
            mma16816(sa[2 * pp],     ah, &bl[0]);
            mma16816(sa[2 * pp],     al, &bh[0]);
            mma16816(sa[2 * pp + 1], ah, &bh[2]);
            mma16816(sa[2 * pp + 1], ah, &bl[2]);
            mma16816(sa[2 * pp + 1], al, &bh[2]);
        }
    }

    const int r0 = lane >> 2, c0 = (lane & 3) * 2;
    const int i0a = it * 64 + w * 16 + r0;
    const int i1a = i0a + 8;
#pragma unroll
    for (int nt = 0; nt < 8; nt++) {
        int j0 = jt * 64 + nt * 8 + c0;
        int j1 = j0 + 1;
        float v00 = fmaxf(sa[nt][0] * 0.125f, 0.f);
        float v01 = fmaxf(sa[nt][1] * 0.125f, 0.f);
        float v10 = fmaxf(sa[nt][2] * 0.125f, 0.f);
        float v11 = fmaxf(sa[nt][3] * 0.125f, 0.f);
        if (!(j0 >= 1 && j0 < i0a)) v00 = 0.f;
        if (!(j1 >= 1 && j1 < i0a)) v01 = 0.f;
        if (!(j0 >= 1 && j0 < i1a)) v10 = 0.f;
        if (!(j1 >= 1 && j1 < i1a)) v11 = 0.f;
        *(float2*)&g_S[((size_t)(b * NT) + i0a) * NT + j0] = make_float2(v00, v01);
        *(float2*)&g_S[((size_t)(b * NT) + i1a) * NT + j0] = make_float2(v10, v11);
    }
}

// ---------------------------------------------------------------------------
// Column scan:  F[b,i,j] = sum_{i'<i} S[b,i',j]
// ---------------------------------------------------------------------------
__global__ __launch_bounds__(256) void colsum_kernel()
{
    int j = blockIdx.x * 256 + threadIdx.x;
    int b = blockIdx.y >> 6, ch = blockIdx.y & 63;
    const float* p = g_S + ((size_t)(b * NT) + ch * CHROWS) * NT + j;
    float s = 0.f;
    for (int r = 0; r < CHROWS; r++) s += p[(size_t)r * NT];
    g_csum[(b * NCHUNK + ch) * NT + j] = s;
}

__global__ __launch_bounds__(256) void scan_kernel()
{
    int j = blockIdx.x * 256 + threadIdx.x;
    int b = blockIdx.y >> 6, ch = blockIdx.y & 63;
    float run = 0.f;
    for (int c = 0; c < ch; c++) run += g_csum[(b * NCHUNK + c) * NT + j];
    size_t base = ((size_t)(b * NT) + ch * CHROWS) * NT + j;
    for (int r = 0; r < CHROWS; r++) {
        size_t idx = base + (size_t)r * NT;
        float sv = g_S[idx];
        g_F[idx] = run;
        run += sv;
    }
}

// ---------------------------------------------------------------------------
// MMA flash attention, 3-stage cp.async KV pipeline, one barrier per kt.
// Fused y hi/lo bf16 output.
// ---------------------------------------------------------------------------
#define QT_B 16384
#define KVT_B 8192
#define KVBUF_B (4 * KVT_B)
#define ATT_SMEM (2 * QT_B + 3 * KVBUF_B)   // 131072

__global__ __launch_bounds__(256, 1) void attn_mma()
{
    extern __shared__ char smc[];
    const uint32_t s_qh = smem_u32(smc);
    const uint32_t s_ql = s_qh + QT_B;
    const uint32_t s_kv0 = s_ql + QT_B;

    const int qi = gridDim.x - 1 - blockIdx.x;
    const int h = blockIdx.y, b = blockIdx.z;
    const int tid = threadIdx.x;
    const int w = tid >> 5, lane = tid & 31;
    const int g = lane >> 2, t4 = lane & 3;
    const int i0 = qi * 128;

    const float SCL = 0.125f * 1.44269504f;
    const float FL2 = 1.44269504f;

    auto issue_kv = [&](int kt) {
        const uint32_t kvb = s_kv0 + (kt % 3) * KVBUF_B;
        const size_t rb = ((size_t)(b * NT) + kt * 64) * QKVW + h * 64;
#pragma unroll
        for (int u = 0; u < 8; u++) {
            int t = u >> 1;
            int rem = ((u & 1) << 8) + tid;
            int row = rem >> 3, cg = rem & 7;
            size_t off = rb + (size_t)row * QKVW + ((t >> 1) ? 1536 : 768) + cg * 8;
            const __nv_bfloat16* src = ((t & 1) ? g_kvl : g_kvh) + off;
            uint32_t dst = kvb + t * KVT_B + row * 128 + ((cg ^ (row & 7)) << 4);
            cp16(dst, src);
        }
        asm volatile("cp.async.commit_group;" ::: "memory");
    };

    // group 0: Q + kv0
    {
        const size_t qbase = ((size_t)(b * NT) + i0) * QKVW + h * 64;
#pragma unroll
        for (int u = 0; u < 8; u++) {
            int half = u >> 2;
            int rem = ((u & 3) << 8) + tid;
            int row = rem >> 3, cg = rem & 7;
            const __nv_bfloat16* src =
                (half ? g_kvl : g_kvh) + qbase + (size_t)row * QKVW + cg * 8;
            uint32_t dst = (half ? s_ql : s_qh) + row * 128 + ((cg ^ (row & 7)) << 4);
            cp16(dst, src);
        }
        const size_t rb = ((size_t)(b * NT)) * QKVW + h * 64;
#pragma unroll
        for (int u = 0; u < 8; u++) {
            int t = u >> 1;
            int rem = ((u & 1) << 8) + tid;
            int row = rem >> 3, cg = rem & 7;
            size_t off = rb + (size_t)row * QKVW + ((t >> 1) ? 1536 : 768) + cg * 8;
            const __nv_bfloat16* src = ((t & 1) ? g_kvl : g_kvh) + off;
            uint32_t dst = s_kv0 + t * KVT_B + row * 128 + ((cg ^ (row & 7)) << 4);
            cp16(dst, src);
        }
        asm volatile("cp.async.commit_group;" ::: "memory");
    }
    const int ktend = 2 * qi + 2;
    issue_kv(1);                      // ktend >= 2 always

    uint32_t qfh[4][4], qfl[4][4];
    float yacc[8][4];
#pragma unroll
    for (int nt = 0; nt < 8; nt++)
#pragma unroll
        for (int e = 0; e < 4; e++) yacc[nt][e] = 0.f;
    float m0 = -INFINITY, m1 = -INFINITY, ls0 = 0.f, ls1 = 0.f;

    const int i_r0 = i0 + w * 16 + g;
    const int i_r1 = i_r0 + 8;
    const int rl = lane & 7, s8 = (lane >> 3) & 1, s16 = lane >> 4;

    for (int kt = 0; kt < ktend; kt++) {
        if (kt + 1 < ktend) {
            asm volatile("cp.async.wait_group 1;" ::: "memory");
        } else {
            asm volatile("cp.async.wait_group 0;" ::: "memory");
        }
        __syncthreads();
        if (kt + 2 < ktend) issue_kv(kt + 2);

        if (kt == 0) {
            int qrow = w * 16 + (lane & 15);
            int qs = (lane >> 4) & 1;
#pragma unroll
            for (int s = 0; s < 4; s++) {
                int cg = 2 * s + qs;
                uint32_t a = (uint32_t)(qrow * 128) + ((cg ^ (qrow & 7)) << 4);
                ldsm_x4(qfh[s], s_qh + a);
                ldsm_x4(qfl[s], s_ql + a);
            }
        }

        const uint32_t kh = s_kv0 + (kt % 3) * KVBUF_B;
        const uint32_t kl = kh + KVT_B;
        const uint32_t vh = kh + 2 * KVT_B;
        const uint32_t vl = kh + 3 * KVT_B;

        // ---- S = Q K^T (3-pass split) ----
        float sa[8][4];
#pragma unroll
        for (int nt = 0; nt < 8; nt++)
#pragma unroll
            for (int e = 0; e < 4; e++) sa[nt][e] = 0.f;

#pragma unroll
        for (int s = 0; s < 4; s++) {
            const int cgk = 2 * s + s8;
            const uint32_t koff = (uint32_t)((cgk ^ rl) << 4);
#pragma unroll
            for (int p = 0; p < 4; p++) {
                uint32_t addr = (uint32_t)((((2 * p + s16) * 8 + rl) * 128)) + koff;
                uint32_t bh[4], bl[4];
                ldsm_x4(bh, kh + addr);
                ldsm_x4(bl, kl + addr);
                mma16816(sa[2 * p],     qfh[s], &bh[0]);
                mma16816(sa[2 * p],     qfh[s], &bl[0]);
                mma16816(sa[2 * p],     qfl[s], &bh[0]);
                mma16816(sa[2 * p + 1], qfh[s], &bh[2]);
                mma16816(sa[2 * p + 1], qfh[s], &bl[2]);
                mma16816(sa[2 * p + 1], qfl[s], &bh[2]);
            }
        }

        // ---- softmax (base-2), logits = sa*SCL - F*FL2 ----
        const float* F0 = g_F + ((size_t)(b * NT) + i_r0) * NT + kt * 64 + 2 * t4;
        const float* F1 = F0 + (size_t)8 * NT;
        const bool edge = (kt >= 2 * qi);
        const int jb = kt * 64 + 2 * t4;
        float mt0 = -INFINITY, mt1 = -INFINITY;
#pragma unroll
        for (int nt = 0; nt < 8; nt++) {
            float2 f0 = *(const float2*)(F0 + nt * 8);
            float2 f1 = *(const float2*)(F1 + nt * 8);
            float v0 = sa[nt][0] * SCL - f0.x * FL2;
            float v1 = sa[nt][1] * SCL - f0.y * FL2;
            float v2 = sa[nt][2] * SCL - f1.x * FL2;
            float v3 = sa[nt][3] * SCL - f1.y * FL2;
            if (edge) {
                int j0 = jb + nt * 8;
                if (j0 > i_r0) v0 = -INFINITY;
                if (j0 + 1 > i_r0) v1 = -INFINITY;
                if (j0 > i_r1) v2 = -INFINITY;
                if (j0 + 1 > i_r1) v3 = -INFINITY;
            }
            sa[nt][0] = v0; sa[nt][1] = v1; sa[nt][2] = v2; sa[nt][3] = v3;
            mt0 = fmaxf(mt0, fmaxf(v0, v1));
            mt1 = fmaxf(mt1, fmaxf(v2, v3));
        }
        mt0 = fmaxf(mt0, __shfl_xor_sync(0xffffffffu, mt0, 1));
        mt0 = fmaxf(mt0, __shfl_xor_sync(0xffffffffu, mt0, 2));
        mt1 = fmaxf(mt1, __shfl_xor_sync(0xffffffffu, mt1, 1));
        mt1 = fmaxf(mt1, __shfl_xor_sync(0xffffffffu, mt1, 2));
        float mn0 = fmaxf(m0, mt0), mn1 = fmaxf(m1, mt1);
        float sc0 = ex2f(m0 - mn0), sc1 = ex2f(m1 - mn1);
        m0 = mn0; m1 = mn1;

        uint32_t pfh01[8], pfh23[8], pfl01[8], pfl23[8];
        float rs0 = 0.f, rs1 = 0.f;
#pragma unroll
        for (int nt = 0; nt < 8; nt++) {
            float p0 = ex2f(sa[nt][0] - m0);
            float p1 = ex2f(sa[nt][1] - m0);
            float p2 = ex2f(sa[nt][2] - m1);
            float p3 = ex2f(sa[nt][3] - m1);
            rs0 += p0 + p1; rs1 += p2 + p3;
            uint32_t h01 = pack_bf16x2(p0, p1);
            uint32_t h23 = pack_bf16x2(p2, p3);
            pfh01[nt] = h01; pfh23[nt] = h23;
            pfl01[nt] = pack_bf16x2(p0 - bf16lo_f(h01), p1 - bf16hi_f(h01));
            pfl23[nt] = pack_bf16x2(p2 - bf16lo_f(h23), p3 - bf16hi_f(h23));
        }
        ls0 = ls0 * sc0 + rs0;
        ls1 = ls1 * sc1 + rs1;
#pragma unroll
        for (int nt = 0; nt < 8; nt++) {
            yacc[nt][0] *= sc0; yacc[nt][1] *= sc0;
            yacc[nt][2] *= sc1; yacc[nt][3] *= sc1;
        }

        // ---- y += P V (3-pass split), V via ldsm trans ----
#pragma unroll
        for (int s = 0; s < 4; s++) {
            uint32_t ah[4] = { pfh01[2 * s], pfh23[2 * s], pfh01[2 * s + 1], pfh23[2 * s + 1] };
            uint32_t al[4] = { pfl01[2 * s], pfl23[2 * s], pfl01[2 * s + 1], pfl23[2 * s + 1] };
            const uint32_t vrow = (uint32_t)((16 * s + s8 * 8 + rl) * 128);
#pragma unroll
            for (int p = 0; p < 4; p++) {
                uint32_t addr = vrow + (uint32_t)((((2 * p + s16)) ^ rl) << 4);
                uint32_t vhf[4], vlf[4];
                ldsm_x4t(vhf, vh + addr);
                ldsm_x4t(vlf, vl + addr);
                mma16816(yacc[2 * p],     ah, &vhf[0]);
                mma16816(yacc[2 * p],     ah, &vlf[0]);
                mma16816(yacc[2 * p],     al, &vhf[0]);
                mma16816(yacc[2 * p + 1], ah, &vhf[2]);
                mma16816(yacc[2 * p + 1], ah, &vlf[2]);
                mma16816(yacc[2 * p + 1], al, &vhf[2]);
            }
        }
    }

    // ---- finalize: y fp32 + hi/lo bf16 ----
    ls0 += __shfl_xor_sync(0xffffffffu, ls0, 1);
    ls0 += __shfl_xor_sync(0xffffffffu, ls0, 2);
    ls1 += __shfl_xor_sync(0xffffffffu, ls1, 1);
    ls1 += __shfl_xor_sync(0xffffffffu, ls1, 2);
    float inv0 = 1.0f / ls0, inv1 = 1.0f / ls1;
    const size_t r0o = ((size_t)(b * NT) + i_r0) * (NH * ND) + h * 64 + 2 * t4;
    const size_t r1o = ((size_t)(b * NT) + i_r1) * (NH * ND) + h * 64 + 2 * t4;
#pragma unroll
    for (int nt = 0; nt < 8; nt++) {
        float v0 = yacc[nt][0] * inv0, v1 = yacc[nt][1] * inv0;
        float v2 = yacc[nt][2] * inv1, v3 = yacc[nt][3] * inv1;
        *(float2*)&g_y[r0o + nt * 8] = make_float2(v0, v1);
        *(float2*)&g_y[r1o + nt * 8] = make_float2(v2, v3);
        uint32_t h0 = pack_bf16x2(v0, v1);
        uint32_t h1 = pack_bf16x2(v2, v3);
        *(uint32_t*)&g_yh[r0o + nt * 8] = h0;
        *(uint32_t*)&g_yh[r1o + nt * 8] = h1;
        *(uint32_t*)&g_yl[r0o + nt * 8] =
            pack_bf16x2(v0 - bf16lo_f(h0), v1 - bf16hi_f(h0));
        *(uint32_t*)&g_yl[r1o + nt * 8] =
            pack_bf16x2(v2 - bf16lo_f(h1), v3 - bf16hi_f(h1));
    }
}

// ---------------------------------------------------------------------------
extern "C" void kernel_launch(void* const* d_in, const int* in_sizes, int n_in,
                              void* d_out, int out_size)
{
    (void)in_sizes; (void)n_in; (void)out_size;
    const float* x      = (const float*)d_in[0];
    const float* w_attn = (const float*)d_in[1];
    const float* b_attn = (const float*)d_in[2];
    const float* w_proj = (const float*)d_in[3];
    const float* b_proj = (const float*)d_in[4];
    float* out = (float*)d_out;

    float *qkv = nullptr;
    cudaGetSymbolAddress((void**)&qkv, g_qkv);
    __nv_bfloat16 *xh, *xl, *wah, *wal, *wph, *wpl, *yh, *yl, *kvh, *kvl;
    cudaGetSymbolAddress((void**)&xh, g_xh);   cudaGetSymbolAddress((void**)&xl, g_xl);
    cudaGetSymbolAddress((void**)&wah, g_wah); cudaGetSymbolAddress((void**)&wal, g_wal);
    cudaGetSymbolAddress((void**)&wph, g_wph); cudaGetSymbolAddress((void**)&wpl, g_wpl);
    cudaGetSymbolAddress((void**)&yh, g_yh);   cudaGetSymbolAddress((void**)&yl, g_yl);
    cudaGetSymbolAddress((void**)&kvh, g_kvh); cudaGetSymbolAddress((void**)&kvl, g_kvl);

    cudaFuncSetAttribute(gemm_mma,
                         cudaFuncAttributeMaxDynamicSharedMemorySize, GEMM_SMEM);
    cudaFuncSetAttribute(attn_mma,
                         cudaFuncAttributeMaxDynamicSharedMemorySize, ATT_SMEM);

    // 0) split-bf16 conversions of x, w_attn, w_proj
    {
        int n4x = (NB * NT * NC) / 4;
        convert_hilo<<<(n4x + 255) / 256, 256>>>(x, xh, xl, n4x);
        int n4a = (QKVW * NC) / 4;
        convert_hilo<<<(n4a + 255) / 256, 256>>>(w_attn, wah, wal, n4a);
        int n4p = (NC * NC) / 4;
        convert_hilo<<<(n4p + 255) / 256, 256>>>(w_proj, wph, wpl, n4p);
    }

    // 1) QKV projection (+ fused hi/lo bf16 output)
    gemm_mma<<<dim3(QKVW / 128, (NB * NT) / 128), 256, GEMM_SMEM>>>(
        xh, xl, wah, wal, b_attn, qkv, kvh, kvl, NB * NT, QKVW, NC);

    // 2) head-0 masked relu scores (mma) -> g_S
    score0_mma<<<dim3(NT / 64, NT / 64, NB), 128>>>();

    // 3) exclusive column cumsum -> g_F
    colsum_kernel<<<dim3(NT / 256, NB * NCHUNK), 256>>>();
    scan_kernel<<<dim3(NT / 256, NB * NCHUNK), 256>>>();

    // 4) MMA flash attention (3-stage pipeline) -> g_y + g_yh/g_yl
    attn_mma<<<dim3(NT / 128, NH, NB), 256, ATT_SMEM>>>();

    // 5) output projection: [4096,768] x [768,768]^T -> out
    gemm_mma<<<dim3(NC / 128, (NB * NT) / 128), 256, GEMM_SMEM>>>(
        yh, yl, wph, wpl, b_proj, out, nullptr, nullptr, NB * NT, NC, NC);
}